// round 6
// baseline (speedup 1.0000x reference)
#include <cuda_runtime.h>
#include <cuda_fp16.h>
#include <cstdint>

#define BATCH 2
#define SEQ   4096
#define DIM   512
#define MTOT  (BATCH*SEQ)   // 8192

// ---------------------------------------------------------------------------
// Scratch (device globals; no allocations allowed).  All fp16.
// ---------------------------------------------------------------------------
__device__ __align__(128) uint16_t g_xh [MTOT*DIM], g_xl [MTOT*DIM];
__device__ __align__(128) uint16_t g_Wqh[DIM*DIM];
__device__ __align__(128) uint16_t g_Wkh[DIM*DIM];
__device__ __align__(128) uint16_t g_Wvh[DIM*DIM];
__device__ __align__(128) uint16_t g_Qh [MTOT*DIM];
__device__ __align__(128) uint16_t g_Kh [MTOT*DIM];
__device__ __align__(128) uint16_t g_VTh[MTOT*DIM];                  // [B][DIM][SEQ]
__device__ __align__(128) uint16_t g_Ph [(long long)BATCH*SEQ*SEQ];  // exp(scores)
__device__ __align__(128) float    g_RSum[MTOT];                     // softmax row sums

// ---------------------------------------------------------------------------
// PTX helpers (sm_80-era ISA only)
// ---------------------------------------------------------------------------
__device__ __forceinline__ uint32_t smem_u32(const void* p) {
    uint32_t a;
    asm("{ .reg .u64 t; cvta.to.shared.u64 t, %1; cvt.u32.u64 %0, t; }"
        : "=r"(a) : "l"(p));
    return a;
}
__device__ __forceinline__ void cp_async16(uint32_t saddr, const void* gptr) {
    asm volatile("cp.async.cg.shared.global [%0], [%1], 16;"
                 :: "r"(saddr), "l"(gptr) : "memory");
}
#define CP_COMMIT()  asm volatile("cp.async.commit_group;" ::: "memory")
#define CP_WAIT(n)   asm volatile("cp.async.wait_group %0;" :: "n"(n) : "memory")

__device__ __forceinline__ void ldsm_x4(uint32_t* r, uint32_t addr) {
    asm volatile("ldmatrix.sync.aligned.m8n8.x4.shared.b16 {%0,%1,%2,%3}, [%4];"
                 : "=r"(r[0]), "=r"(r[1]), "=r"(r[2]), "=r"(r[3]) : "r"(addr));
}
__device__ __forceinline__ void mma_f16(float* c, const uint32_t* a, const uint32_t* b) {
    asm volatile(
        "mma.sync.aligned.m16n8k16.row.col.f32.f16.f16.f32 "
        "{%0,%1,%2,%3}, {%4,%5,%6,%7}, {%8,%9}, {%0,%1,%2,%3};"
        : "+f"(c[0]), "+f"(c[1]), "+f"(c[2]), "+f"(c[3])
        : "r"(a[0]), "r"(a[1]), "r"(a[2]), "r"(a[3]), "r"(b[0]), "r"(b[1]));
}

// FMA-pipe exp (deg-6 2^f poly, rel err ~2e-7).  |x| < 30.
__device__ __forceinline__ float exp_fma(float x) {
    const float r = x * 1.4426950408889634f;
    const float i = rintf(r);
    const float f = r - i;
    float p = 1.5405906e-4f;
    p = fmaf(p, f, 1.3333558e-3f);
    p = fmaf(p, f, 9.6181291e-3f);
    p = fmaf(p, f, 5.5504109e-2f);
    p = fmaf(p, f, 2.4022651e-1f);
    p = fmaf(p, f, 6.9314718e-1f);
    p = fmaf(p, f, 1.0f);
    return p * __int_as_float(((int)i + 127) << 23);
}

// ---------------------------------------------------------------------------
// fp16 split GEMM on mma.sync:  C[M,N] = alpha * (A[M,K] @ B[N,K]^T)
//  NMMA=2 : A split hi+lo (ah*bh + al*bh)  — projections
//  NMMA=1 : hi only       (ah*bh)         — scores / PV
// BM=BN=128, BK=64, 128 threads (4 warps, 2x2), warp tile 64x64.
// Double-buffered cp.async, pitch-144B rows (conflict-free ldmatrix).
// EPI: 2 = fp16 C;  3 = fp16 C in V^T layout [B][DIM][SEQ];
//      4 = fp16 exp(C) + atomic row-sum accumulation into rsum;
//      5 = fp32 C / rsum[row]  (PV with folded softmax normalization)
// ---------------------------------------------------------------------------
constexpr int PITCH  = 144;              // 128B data + 16B pad
constexpr int TILE_B = 128 * PITCH;      // 18432 B per tile

template <int EPI, int NMMA>
__global__ __launch_bounds__(128, 2)
void tc_gemm(const uint16_t* __restrict__ Ah, const uint16_t* __restrict__ Al,
             const uint16_t* __restrict__ Bh,
             uint16_t* __restrict__ Ch, float* __restrict__ C,
             float* __restrict__ rsum,
             int M, int N, int K,
             long long sA, long long sB, long long sC, float alpha)
{
    constexpr int NT      = NMMA + 1;
    constexpr int STAGE_B = NT * TILE_B;

    extern __shared__ __align__(128) char smem[];
    const uint32_t sb = smem_u32(smem);
    const int tid  = threadIdx.x;
    const int wid  = tid >> 5;
    const int lane = tid & 31;
    const int z = blockIdx.z;
    Ah += z * sA;  Bh += z * sB;
    if (NMMA == 2) Al += z * sA;
    if (EPI == 4) { Ch += z * sC;  rsum += z * M; }
    if (EPI == 5) { C  += z * sC;  rsum += z * M; }

    const long long bm = (long long)blockIdx.y * 128;
    const long long bn = (long long)blockIdx.x * 128;

    const uint16_t* srcs[NT];
    if (NMMA == 2) {
        srcs[0] = Ah + bm * K;  srcs[1] = Al + bm * K;  srcs[2] = Bh + bn * K;
    } else {
        srcs[0] = Ah + bm * K;  srcs[1] = Bh + bn * K;
    }

    // per tile: 128 rows x 128B = 1024 16B-chunks; 128 threads -> 8 each
    auto issue_load = [&](int it, int buf) {
        const uint32_t stage = sb + buf * STAGE_B;
        const int k0 = it * 64;
#pragma unroll
        for (int t = 0; t < NT; ++t) {
            const uint16_t* src = srcs[t] + k0;
#pragma unroll
            for (int c = 0; c < 8; ++c) {
                const int chunk = tid + c * 128;
                const int row = chunk >> 3;
                const int sub = chunk & 7;
                cp_async16(stage + t * TILE_B + row * PITCH + sub * 16,
                           src + (long long)row * K + sub * 8);
            }
        }
    };

    const int warpM = wid >> 1;        // 0..1 (64 rows)
    const int warpN = wid & 1;         // 0..1 (64 cols)
    const int aRow = warpM * 64 + (lane & 15);
    const int bRow = warpN * 64 + (lane & 15);
    const int xOff = (lane >> 4) * 16;

    float acc[4][8][4];
#pragma unroll
    for (int mi = 0; mi < 4; ++mi)
#pragma unroll
        for (int ni = 0; ni < 8; ++ni)
#pragma unroll
            for (int q = 0; q < 4; ++q) acc[mi][ni][q] = 0.f;

    const int niter = K / 64;
    issue_load(0, 0); CP_COMMIT();
    issue_load(1, 1); CP_COMMIT();

    for (int it = 0; it < niter; ++it) {
        const int buf = it & 1;
        CP_WAIT(1);
        __syncthreads();

        const uint32_t stage  = sb + buf * STAGE_B;
        const uint32_t aBase  = stage + aRow * PITCH + xOff;
        const uint32_t aBaseL = stage + TILE_B + aRow * PITCH + xOff;
        const uint32_t bBase  = stage + (NT - 1) * TILE_B + bRow * PITCH + xOff;

#pragma unroll
        for (int ks = 0; ks < 4; ++ks) {
            uint32_t a[4][4], b[8][2];
#pragma unroll
            for (int mi = 0; mi < 4; ++mi)
                ldsm_x4(a[mi], aBase + mi * (16 * PITCH) + ks * 32);
#pragma unroll
            for (int nj = 0; nj < 4; ++nj) {
                uint32_t t4[4];
                ldsm_x4(t4, bBase + nj * (16 * PITCH) + ks * 32);
                b[2 * nj][0]     = t4[0];  b[2 * nj][1]     = t4[2];
                b[2 * nj + 1][0] = t4[1];  b[2 * nj + 1][1] = t4[3];
            }
#pragma unroll
            for (int mi = 0; mi < 4; ++mi)
#pragma unroll
                for (int ni = 0; ni < 8; ++ni)
                    mma_f16(acc[mi][ni], a[mi], b[ni]);
            if (NMMA == 2) {
                uint32_t al[4][4];
#pragma unroll
                for (int mi = 0; mi < 4; ++mi)
                    ldsm_x4(al[mi], aBaseL + mi * (16 * PITCH) + ks * 32);
#pragma unroll
                for (int mi = 0; mi < 4; ++mi)
#pragma unroll
                    for (int ni = 0; ni < 8; ++ni)
                        mma_f16(acc[mi][ni], al[mi], b[ni]);
            }
        }
        __syncthreads();
        if (it + 2 < niter) issue_load(it + 2, buf);
        CP_COMMIT();
    }

    // ---- epilogue ----
#pragma unroll
    for (int mi = 0; mi < 4; ++mi) {
#pragma unroll
        for (int h = 0; h < 2; ++h) {
            const long long row = bm + warpM * 64 + (lane >> 2) + mi * 16 + h * 8;
            float rs = 0.f, inv = 0.f;
            if (EPI == 5) inv = 1.f / rsum[row];
#pragma unroll
            for (int ni = 0; ni < 8; ++ni) {
                const int col = (int)bn + warpN * 64 + (lane & 3) * 2 + ni * 8;
                const float f0 = acc[mi][ni][2 * h]     * alpha;
                const float f1 = acc[mi][ni][2 * h + 1] * alpha;
                if (EPI == 2) {
                    __half2 v; v.x = __float2half_rn(f0); v.y = __float2half_rn(f1);
                    *reinterpret_cast<__half2*>(Ch + row * N + col) = v;
                } else if (EPI == 3) {
                    const long long bimg = (row >> 12) * ((long long)DIM * SEQ);
                    const int s = (int)(row & (SEQ - 1));
                    reinterpret_cast<__half*>(Ch)[bimg + (long long)col * SEQ + s] =
                        __float2half_rn(f0);
                    reinterpret_cast<__half*>(Ch)[bimg + (long long)(col + 1) * SEQ + s] =
                        __float2half_rn(f1);
                } else if (EPI == 4) {
                    const float e0 = __expf(f0);       // MUFU pipe
                    const float e1 = exp_fma(f1);      // FMA pipe
                    rs += e0 + e1;
                    __half2 v; v.x = __float2half_rn(e0); v.y = __float2half_rn(e1);
                    *reinterpret_cast<__half2*>(Ch + row * N + col) = v;
                } else {
                    float2 v; v.x = f0 * inv; v.y = f1 * inv;
                    *reinterpret_cast<float2*>(C + row * N + col) = v;
                }
            }
            if (EPI == 4) {
                rs += __shfl_xor_sync(0xffffffffu, rs, 1);
                rs += __shfl_xor_sync(0xffffffffu, rs, 2);
                if ((lane & 3) == 0) atomicAdd(rsum + row, rs);
            }
        }
    }
}

// ---------------------------------------------------------------------------
// fp32 -> fp16 hi/lo split (elementwise, float4 vectorized)
// ---------------------------------------------------------------------------
__global__ __launch_bounds__(256)
void split_kernel(const float* __restrict__ in,
                  uint16_t* __restrict__ hi, uint16_t* __restrict__ lo, int n4)
{
    const int i = blockIdx.x * blockDim.x + threadIdx.x;
    if (i >= n4) return;
    float4 v = *reinterpret_cast<const float4*>(in + 4 * (long long)i);
    float f[4] = { v.x, v.y, v.z, v.w };
    __half h[4], l[4];
#pragma unroll
    for (int q = 0; q < 4; ++q) {
        h[q] = __float2half_rn(f[q]);
        l[q] = __float2half_rn(f[q] - __half2float(h[q]));
    }
    __half2 h01, h23, l01, l23;
    h01.x = h[0]; h01.y = h[1]; h23.x = h[2]; h23.y = h[3];
    l01.x = l[0]; l01.y = l[1]; l23.x = l[2]; l23.y = l[3];
    *reinterpret_cast<__half2*>(hi + 4 * (long long)i)     = h01;
    *reinterpret_cast<__half2*>(hi + 4 * (long long)i + 2) = h23;
    *reinterpret_cast<__half2*>(lo + 4 * (long long)i)     = l01;
    *reinterpret_cast<__half2*>(lo + 4 * (long long)i + 2) = l23;
}

// ---------------------------------------------------------------------------
// W[i][o] -> W^T[o][i] as fp16.  512x512.
// ---------------------------------------------------------------------------
__global__ __launch_bounds__(256)
void wtrans_f16(const float* __restrict__ W, uint16_t* __restrict__ Th)
{
    __shared__ float t[32][33];
    const int bx = blockIdx.x * 32;   // o
    const int by = blockIdx.y * 32;   // i
    const int tx = threadIdx.x, ty = threadIdx.y;   // 32 x 8
#pragma unroll
    for (int r = ty; r < 32; r += 8)
        t[r][tx] = W[(by + r) * DIM + bx + tx];
    __syncthreads();
#pragma unroll
    for (int r = ty; r < 32; r += 8)
        reinterpret_cast<__half*>(Th)[(bx + r) * DIM + by + tx] =
            __float2half_rn(t[tx][r]);
}

// ---------------------------------------------------------------------------
__global__ __launch_bounds__(256)
void zero_rsum(float* __restrict__ rsum)
{
    rsum[blockIdx.x * 256 + threadIdx.x] = 0.f;
}

// ---------------------------------------------------------------------------
extern "C" void kernel_launch(void* const* d_in, const int* in_sizes, int n_in,
                              void* d_out, int out_size)
{
    const float* x  = (const float*)d_in[0];
    const float* Wq = (const float*)d_in[1];
    const float* Wk = (const float*)d_in[2];
    const float* Wv = (const float*)d_in[3];
    float* out = (float*)d_out;

    uint16_t *xh, *xl, *Wqh, *Wkh, *Wvh, *Qh, *Kh, *VTh, *Ph;
    float* rsum;
    cudaGetSymbolAddress((void**)&xh, g_xh);   cudaGetSymbolAddress((void**)&xl, g_xl);
    cudaGetSymbolAddress((void**)&Wqh, g_Wqh);
    cudaGetSymbolAddress((void**)&Wkh, g_Wkh);
    cudaGetSymbolAddress((void**)&Wvh, g_Wvh);
    cudaGetSymbolAddress((void**)&Qh, g_Qh);
    cudaGetSymbolAddress((void**)&Kh, g_Kh);
    cudaGetSymbolAddress((void**)&VTh, g_VTh);
    cudaGetSymbolAddress((void**)&Ph, g_Ph);
    cudaGetSymbolAddress((void**)&rsum, g_RSum);

    constexpr int SM2 = 2 * 3 * TILE_B;   // 110592 (projection, NT=3)
    constexpr int SM1 = 2 * 2 * TILE_B;   // 73728  (scores/PV, NT=2)
    cudaFuncSetAttribute(tc_gemm<2, 2>, cudaFuncAttributeMaxDynamicSharedMemorySize, SM2);
    cudaFuncSetAttribute(tc_gemm<3, 2>, cudaFuncAttributeMaxDynamicSharedMemorySize, SM2);
    cudaFuncSetAttribute(tc_gemm<4, 1>, cudaFuncAttributeMaxDynamicSharedMemorySize, SM1);
    cudaFuncSetAttribute(tc_gemm<5, 1>, cudaFuncAttributeMaxDynamicSharedMemorySize, SM1);

    // 1. prep: split x to fp16 hi/lo, transpose W to fp16, zero row sums
    split_kernel<<<(MTOT * DIM / 4 + 255) / 256, 256>>>(x, xh, xl, MTOT * DIM / 4);
    wtrans_f16<<<dim3(16, 16), dim3(32, 8)>>>(Wq, Wqh);
    wtrans_f16<<<dim3(16, 16), dim3(32, 8)>>>(Wk, Wkh);
    wtrans_f16<<<dim3(16, 16), dim3(32, 8)>>>(Wv, Wvh);
    zero_rsum<<<MTOT / 256, 256>>>(rsum);

    // 2. projections (fp16 2-MMA): Q,K row-major; V in V^T layout
    dim3 gp(DIM / 128, MTOT / 128, 1);
    tc_gemm<2, 2><<<gp, 128, SM2>>>(xh, xl, Wqh, Qh, nullptr, nullptr,
                                    MTOT, DIM, DIM, 0, 0, 0, 1.f);
    tc_gemm<2, 2><<<gp, 128, SM2>>>(xh, xl, Wkh, Kh, nullptr, nullptr,
                                    MTOT, DIM, DIM, 0, 0, 0, 1.f);
    tc_gemm<3, 2><<<gp, 128, SM2>>>(xh, xl, Wvh, VTh, nullptr, nullptr,
                                    MTOT, DIM, DIM, 0, 0, 0, 1.f);

    // 3. scores (fp16 1-MMA) + fused exp + atomic row sums
    const float scale = 0.044194173824159216f;   // 1/sqrt(512)
    dim3 gs(SEQ / 128, SEQ / 128, BATCH);
    tc_gemm<4, 1><<<gs, 128, SM1>>>(Qh, nullptr, Kh, Ph, nullptr, rsum,
                                    SEQ, SEQ, DIM,
                                    (long long)SEQ * DIM, (long long)SEQ * DIM,
                                    (long long)SEQ * SEQ, scale);

    // 4. context (fp16 1-MMA), normalization folded: out = (Ph VTh^T) / rsum
    dim3 gv(DIM / 128, SEQ / 128, BATCH);
    tc_gemm<5, 1><<<gv, 128, SM1>>>(Ph, nullptr, VTh, nullptr, out, rsum,
                                    SEQ, DIM, SEQ,
                                    (long long)SEQ * SEQ, (long long)DIM * SEQ,
                                    (long long)SEQ * DIM, 1.f);

    (void)in_sizes; (void)n_in; (void)out_size;
}

// round 7
// speedup vs baseline: 1.5885x; 1.5885x over previous
#include <cuda_runtime.h>
#include <cuda_fp16.h>
#include <cstdint>

#define BATCH 2
#define SEQ   4096
#define DIM   512
#define MTOT  (BATCH*SEQ)   // 8192

// ---------------------------------------------------------------------------
// Scratch (device globals; no allocations allowed).  All fp16.
// ---------------------------------------------------------------------------
__device__ __align__(128) uint16_t g_xh [MTOT*DIM], g_xl [MTOT*DIM];
__device__ __align__(128) uint16_t g_Wqh[DIM*DIM];
__device__ __align__(128) uint16_t g_Wkh[DIM*DIM];
__device__ __align__(128) uint16_t g_Wvh[DIM*DIM];
__device__ __align__(128) uint16_t g_Qh [MTOT*DIM];
__device__ __align__(128) uint16_t g_Kh [MTOT*DIM];
__device__ __align__(128) uint16_t g_VTh[MTOT*DIM];                  // [B][DIM][SEQ]
__device__ __align__(128) uint16_t g_Ph [(long long)BATCH*SEQ*SEQ];  // exp(scores)
__device__ __align__(128) float    g_RSum[MTOT];                     // softmax row sums

// ---------------------------------------------------------------------------
// PTX helpers (sm_80-era ISA only)
// ---------------------------------------------------------------------------
__device__ __forceinline__ uint32_t smem_u32(const void* p) {
    uint32_t a;
    asm("{ .reg .u64 t; cvta.to.shared.u64 t, %1; cvt.u32.u64 %0, t; }"
        : "=r"(a) : "l"(p));
    return a;
}
__device__ __forceinline__ void cp_async16(uint32_t saddr, const void* gptr) {
    asm volatile("cp.async.cg.shared.global [%0], [%1], 16;"
                 :: "r"(saddr), "l"(gptr) : "memory");
}
#define CP_COMMIT()  asm volatile("cp.async.commit_group;" ::: "memory")
#define CP_WAIT(n)   asm volatile("cp.async.wait_group %0;" :: "n"(n) : "memory")

__device__ __forceinline__ void ldsm_x4(uint32_t* r, uint32_t addr) {
    asm volatile("ldmatrix.sync.aligned.m8n8.x4.shared.b16 {%0,%1,%2,%3}, [%4];"
                 : "=r"(r[0]), "=r"(r[1]), "=r"(r[2]), "=r"(r[3]) : "r"(addr));
}
__device__ __forceinline__ void ldsm_x2(uint32_t* r, uint32_t addr) {
    asm volatile("ldmatrix.sync.aligned.m8n8.x2.shared.b16 {%0,%1}, [%2];"
                 : "=r"(r[0]), "=r"(r[1]) : "r"(addr));
}
__device__ __forceinline__ void mma_f16(float* c, const uint32_t* a, const uint32_t* b) {
    asm volatile(
        "mma.sync.aligned.m16n8k16.row.col.f32.f16.f16.f32 "
        "{%0,%1,%2,%3}, {%4,%5,%6,%7}, {%8,%9}, {%0,%1,%2,%3};"
        : "+f"(c[0]), "+f"(c[1]), "+f"(c[2]), "+f"(c[3])
        : "r"(a[0]), "r"(a[1]), "r"(a[2]), "r"(a[3]), "r"(b[0]), "r"(b[1]));
}

// FMA-pipe exp (deg-6 2^f poly, rel err ~2e-7).  |x| < 30.
__device__ __forceinline__ float exp_fma(float x) {
    const float r = x * 1.4426950408889634f;
    const float i = rintf(r);
    const float f = r - i;
    float p = 1.5405906e-4f;
    p = fmaf(p, f, 1.3333558e-3f);
    p = fmaf(p, f, 9.6181291e-3f);
    p = fmaf(p, f, 5.5504109e-2f);
    p = fmaf(p, f, 2.4022651e-1f);
    p = fmaf(p, f, 6.9314718e-1f);
    p = fmaf(p, f, 1.0f);
    return p * __int_as_float(((int)i + 127) << 23);
}

// ---------------------------------------------------------------------------
// fp16 split GEMM on mma.sync:  C[M,N] = alpha * (A[M,K] @ B[N,K]^T)
//  NMMA=2 : A split hi+lo (ah*bh + al*bh)  — projections
//  NMMA=1 : hi only       (ah*bh)         — scores / PV
// BM=BN=128, BK=32, 256 threads (2x4 warps), warp tile 64x32.   [R5 proven]
// Double-buffered cp.async, pitch-80B smem rows (conflict-free ldmatrix).
// EPI: 2 = fp16 C;  3 = fp16 C in V^T layout [B][DIM][SEQ];
//      4 = fp16 exp(C) + atomic row-sum accumulation into rsum;
//      5 = fp32 C / rsum[row]  (PV with folded softmax normalization)
// ---------------------------------------------------------------------------
constexpr int PITCH  = 80;               // 64B data + 16B pad
constexpr int TILE_B = 128 * PITCH;      // 10240 B per tile

template <int EPI, int NMMA>
__global__ __launch_bounds__(256, 2)
void tc_gemm(const uint16_t* __restrict__ Ah, const uint16_t* __restrict__ Al,
             const uint16_t* __restrict__ Bh,
             uint16_t* __restrict__ Ch, float* __restrict__ C,
             float* __restrict__ rsum,
             int M, int N, int K,
             long long sA, long long sB, long long sC, float alpha)
{
    constexpr int NT      = NMMA + 1;    // tiles per stage: {Ah[,Al],Bh}
    constexpr int STAGE_B = NT * TILE_B;

    extern __shared__ __align__(128) char smem[];
    const uint32_t sb = smem_u32(smem);
    const int tid  = threadIdx.x;
    const int wid  = tid >> 5;
    const int lane = tid & 31;
    const int z = blockIdx.z;
    Ah += z * sA;  Bh += z * sB;
    if (NMMA == 2) Al += z * sA;
    if (EPI == 4) { Ch += z * sC;  rsum += z * M; }
    if (EPI == 5) { C  += z * sC;  rsum += z * M; }

    const long long bm = (long long)blockIdx.y * 128;
    const long long bn = (long long)blockIdx.x * 128;

    const uint16_t* srcs[NT];
    if (NMMA == 2) {
        srcs[0] = Ah + bm * K;  srcs[1] = Al + bm * K;  srcs[2] = Bh + bn * K;
    } else {
        srcs[0] = Ah + bm * K;  srcs[1] = Bh + bn * K;
    }

    // per tile: 128 rows x 64B = 512 16B-chunks; 256 threads -> 2 each
    auto issue_load = [&](int it, int buf) {
        const uint32_t stage = sb + buf * STAGE_B;
        const int k0 = it * 32;
#pragma unroll
        for (int t = 0; t < NT; ++t) {
            const uint16_t* src = srcs[t] + k0;
#pragma unroll
            for (int c = 0; c < 2; ++c) {
                const int chunk = tid + c * 256;        // 0..511
                const int row = chunk >> 2;
                const int c4  = chunk & 3;
                cp_async16(stage + t * TILE_B + row * PITCH + c4 * 16,
                           src + (long long)row * K + c4 * 8);
            }
        }
    };

    const int warpM = wid >> 2;        // 0..1  (64 rows each)
    const int warpN = wid & 3;         // 0..3  (32 cols each)
    const int aRow = warpM * 64 + (lane & 15);
    const int aOff = (lane >> 4) * 16;
    const int bRow = warpN * 32 + (lane & 7);
    const int bOff = ((lane >> 3) & 1) * 16;

    float acc[4][4][4];
#pragma unroll
    for (int mi = 0; mi < 4; ++mi)
#pragma unroll
        for (int ni = 0; ni < 4; ++ni)
#pragma unroll
            for (int q = 0; q < 4; ++q) acc[mi][ni][q] = 0.f;

    const int niter = K / 32;
    issue_load(0, 0); CP_COMMIT();
    issue_load(1, 1); CP_COMMIT();

    for (int it = 0; it < niter; ++it) {
        const int buf = it & 1;
        CP_WAIT(1);
        __syncthreads();

        const uint32_t stage  = sb + buf * STAGE_B;
        const uint32_t aBaseH = stage + aRow * PITCH + aOff;
        const uint32_t aBaseL = stage + TILE_B + aRow * PITCH + aOff;
        const uint32_t bBase  = stage + (NT - 1) * TILE_B + bRow * PITCH + bOff;

#pragma unroll
        for (int ks = 0; ks < 2; ++ks) {
            uint32_t ah[4][4], b[4][2];
#pragma unroll
            for (int mi = 0; mi < 4; ++mi)
                ldsm_x4(ah[mi], aBaseH + mi * (16 * PITCH) + ks * 32);
#pragma unroll
            for (int ni = 0; ni < 4; ++ni)
                ldsm_x2(b[ni], bBase + ni * (8 * PITCH) + ks * 32);
#pragma unroll
            for (int mi = 0; mi < 4; ++mi)
#pragma unroll
                for (int ni = 0; ni < 4; ++ni)
                    mma_f16(acc[mi][ni], ah[mi], b[ni]);
            if (NMMA == 2) {
                uint32_t al[4][4];
#pragma unroll
                for (int mi = 0; mi < 4; ++mi)
                    ldsm_x4(al[mi], aBaseL + mi * (16 * PITCH) + ks * 32);
#pragma unroll
                for (int mi = 0; mi < 4; ++mi)
#pragma unroll
                    for (int ni = 0; ni < 4; ++ni)
                        mma_f16(acc[mi][ni], al[mi], b[ni]);
            }
        }
        __syncthreads();
        if (it + 2 < niter) issue_load(it + 2, buf);
        CP_COMMIT();
    }

    // ---- epilogue ----
#pragma unroll
    for (int mi = 0; mi < 4; ++mi) {
#pragma unroll
        for (int h = 0; h < 2; ++h) {
            const long long row = bm + warpM * 64 + (lane >> 2) + mi * 16 + h * 8;
            float rs = 0.f, inv = 0.f;
            if (EPI == 5) inv = 1.f / rsum[row];
#pragma unroll
            for (int ni = 0; ni < 4; ++ni) {
                const int col = (int)bn + warpN * 32 + (lane & 3) * 2 + ni * 8;
                const float f0 = acc[mi][ni][2 * h]     * alpha;
                const float f1 = acc[mi][ni][2 * h + 1] * alpha;
                if (EPI == 2) {
                    __half2 v; v.x = __float2half_rn(f0); v.y = __float2half_rn(f1);
                    *reinterpret_cast<__half2*>(Ch + row * N + col) = v;
                } else if (EPI == 3) {
                    const long long bimg = (row >> 12) * ((long long)DIM * SEQ);
                    const int s = (int)(row & (SEQ - 1));
                    reinterpret_cast<__half*>(Ch)[bimg + (long long)col * SEQ + s] =
                        __float2half_rn(f0);
                    reinterpret_cast<__half*>(Ch)[bimg + (long long)(col + 1) * SEQ + s] =
                        __float2half_rn(f1);
                } else if (EPI == 4) {
                    const float e0 = __expf(f0);       // MUFU pipe
                    const float e1 = exp_fma(f1);      // FMA pipe
                    rs += e0 + e1;
                    __half2 v; v.x = __float2half_rn(e0); v.y = __float2half_rn(e1);
                    *reinterpret_cast<__half2*>(Ch + row * N + col) = v;
                } else {
                    float2 v; v.x = f0 * inv; v.y = f1 * inv;
                    *reinterpret_cast<float2*>(C + row * N + col) = v;
                }
            }
            if (EPI == 4) {
                rs += __shfl_xor_sync(0xffffffffu, rs, 1);
                rs += __shfl_xor_sync(0xffffffffu, rs, 2);
                if ((lane & 3) == 0) atomicAdd(rsum + row, rs);
            }
        }
    }
}

// ---------------------------------------------------------------------------
// fp32 -> fp16 hi/lo split (elementwise, float4 vectorized)
// ---------------------------------------------------------------------------
__global__ __launch_bounds__(256)
void split_kernel(const float* __restrict__ in,
                  uint16_t* __restrict__ hi, uint16_t* __restrict__ lo, int n4)
{
    const int i = blockIdx.x * blockDim.x + threadIdx.x;
    if (i >= n4) return;
    float4 v = *reinterpret_cast<const float4*>(in + 4 * (long long)i);
    float f[4] = { v.x, v.y, v.z, v.w };
    __half h[4], l[4];
#pragma unroll
    for (int q = 0; q < 4; ++q) {
        h[q] = __float2half_rn(f[q]);
        l[q] = __float2half_rn(f[q] - __half2float(h[q]));
    }
    __half2 h01, h23, l01, l23;
    h01.x = h[0]; h01.y = h[1]; h23.x = h[2]; h23.y = h[3];
    l01.x = l[0]; l01.y = l[1]; l23.x = l[2]; l23.y = l[3];
    *reinterpret_cast<__half2*>(hi + 4 * (long long)i)     = h01;
    *reinterpret_cast<__half2*>(hi + 4 * (long long)i + 2) = h23;
    *reinterpret_cast<__half2*>(lo + 4 * (long long)i)     = l01;
    *reinterpret_cast<__half2*>(lo + 4 * (long long)i + 2) = l23;
}

// ---------------------------------------------------------------------------
// W[i][o] -> W^T[o][i] as fp16.  512x512.
// ---------------------------------------------------------------------------
__global__ __launch_bounds__(256)
void wtrans_f16(const float* __restrict__ W, uint16_t* __restrict__ Th)
{
    __shared__ float t[32][33];
    const int bx = blockIdx.x * 32;   // o
    const int by = blockIdx.y * 32;   // i
    const int tx = threadIdx.x, ty = threadIdx.y;   // 32 x 8
#pragma unroll
    for (int r = ty; r < 32; r += 8)
        t[r][tx] = W[(by + r) * DIM + bx + tx];
    __syncthreads();
#pragma unroll
    for (int r = ty; r < 32; r += 8)
        reinterpret_cast<__half*>(Th)[(bx + r) * DIM + by + tx] =
            __float2half_rn(t[tx][r]);
}

// ---------------------------------------------------------------------------
__global__ __launch_bounds__(256)
void zero_rsum(float* __restrict__ rsum)
{
    rsum[blockIdx.x * 256 + threadIdx.x] = 0.f;
}

// ---------------------------------------------------------------------------
extern "C" void kernel_launch(void* const* d_in, const int* in_sizes, int n_in,
                              void* d_out, int out_size)
{
    const float* x  = (const float*)d_in[0];
    const float* Wq = (const float*)d_in[1];
    const float* Wk = (const float*)d_in[2];
    const float* Wv = (const float*)d_in[3];
    float* out = (float*)d_out;

    uint16_t *xh, *xl, *Wqh, *Wkh, *Wvh, *Qh, *Kh, *VTh, *Ph;
    float* rsum;
    cudaGetSymbolAddress((void**)&xh, g_xh);   cudaGetSymbolAddress((void**)&xl, g_xl);
    cudaGetSymbolAddress((void**)&Wqh, g_Wqh);
    cudaGetSymbolAddress((void**)&Wkh, g_Wkh);
    cudaGetSymbolAddress((void**)&Wvh, g_Wvh);
    cudaGetSymbolAddress((void**)&Qh, g_Qh);
    cudaGetSymbolAddress((void**)&Kh, g_Kh);
    cudaGetSymbolAddress((void**)&VTh, g_VTh);
    cudaGetSymbolAddress((void**)&Ph, g_Ph);
    cudaGetSymbolAddress((void**)&rsum, g_RSum);

    constexpr int SM2 = 2 * 3 * TILE_B;   // 61440 (projection, NT=3)
    constexpr int SM1 = 2 * 2 * TILE_B;   // 40960 (scores/PV, NT=2)
    cudaFuncSetAttribute(tc_gemm<2, 2>, cudaFuncAttributeMaxDynamicSharedMemorySize, SM2);
    cudaFuncSetAttribute(tc_gemm<3, 2>, cudaFuncAttributeMaxDynamicSharedMemorySize, SM2);
    cudaFuncSetAttribute(tc_gemm<4, 1>, cudaFuncAttributeMaxDynamicSharedMemorySize, SM1);
    cudaFuncSetAttribute(tc_gemm<5, 1>, cudaFuncAttributeMaxDynamicSharedMemorySize, SM1);

    // 1. prep: split x to fp16 hi/lo, transpose W to fp16, zero row sums
    split_kernel<<<(MTOT * DIM / 4 + 255) / 256, 256>>>(x, xh, xl, MTOT * DIM / 4);
    wtrans_f16<<<dim3(16, 16), dim3(32, 8)>>>(Wq, Wqh);
    wtrans_f16<<<dim3(16, 16), dim3(32, 8)>>>(Wk, Wkh);
    wtrans_f16<<<dim3(16, 16), dim3(32, 8)>>>(Wv, Wvh);
    zero_rsum<<<MTOT / 256, 256>>>(rsum);

    // 2. projections (fp16 2-MMA): Q,K row-major; V in V^T layout
    dim3 gp(DIM / 128, MTOT / 128, 1);
    tc_gemm<2, 2><<<gp, 256, SM2>>>(xh, xl, Wqh, Qh, nullptr, nullptr,
                                    MTOT, DIM, DIM, 0, 0, 0, 1.f);
    tc_gemm<2, 2><<<gp, 256, SM2>>>(xh, xl, Wkh, Kh, nullptr, nullptr,
                                    MTOT, DIM, DIM, 0, 0, 0, 1.f);
    tc_gemm<3, 2><<<gp, 256, SM2>>>(xh, xl, Wvh, VTh, nullptr, nullptr,
                                    MTOT, DIM, DIM, 0, 0, 0, 1.f);

    // 3. scores (fp16 1-MMA) + fused exp + atomic row sums
    const float scale = 0.044194173824159216f;   // 1/sqrt(512)
    dim3 gs(SEQ / 128, SEQ / 128, BATCH);
    tc_gemm<4, 1><<<gs, 256, SM1>>>(Qh, nullptr, Kh, Ph, nullptr, rsum,
                                    SEQ, SEQ, DIM,
                                    (long long)SEQ * DIM, (long long)SEQ * DIM,
                                    (long long)SEQ * SEQ, scale);

    // 4. context (fp16 1-MMA), normalization folded: out = (Ph VTh^T) / rsum
    dim3 gv(DIM / 128, SEQ / 128, BATCH);
    tc_gemm<5, 1><<<gv, 256, SM1>>>(Ph, nullptr, VTh, nullptr, out, rsum,
                                    SEQ, DIM, SEQ,
                                    (long long)SEQ * SEQ, (long long)DIM * SEQ,
                                    (long long)SEQ * DIM, 1.f);

    (void)in_sizes; (void)n_in; (void)out_size;
}

// round 8
// speedup vs baseline: 1.6434x; 1.0346x over previous
#include <cuda_runtime.h>
#include <cuda_fp16.h>
#include <cstdint>

#define BATCH 2
#define SEQ   4096
#define DIM   512
#define MTOT  (BATCH*SEQ)   // 8192

// ---------------------------------------------------------------------------
// Scratch (device globals; no allocations allowed).  All fp16.
// ---------------------------------------------------------------------------
__device__ __align__(128) uint16_t g_xh [MTOT*DIM], g_xl [MTOT*DIM];
__device__ __align__(128) uint16_t g_Wqh[DIM*DIM];
__device__ __align__(128) uint16_t g_Wkh[DIM*DIM];
__device__ __align__(128) uint16_t g_Wvh[DIM*DIM];
__device__ __align__(128) uint16_t g_Qh [MTOT*DIM];
__device__ __align__(128) uint16_t g_Kh [MTOT*DIM];
__device__ __align__(128) uint16_t g_Vh [MTOT*DIM];                  // row-major [B][SEQ][DIM]
__device__ __align__(128) uint16_t g_Ph [(long long)BATCH*SEQ*SEQ];  // exp(scores)
__device__ __align__(128) float    g_RSum[MTOT];                     // softmax row sums

// ---------------------------------------------------------------------------
// PTX helpers (sm_80-era ISA only)
// ---------------------------------------------------------------------------
__device__ __forceinline__ uint32_t smem_u32(const void* p) {
    uint32_t a;
    asm("{ .reg .u64 t; cvta.to.shared.u64 t, %1; cvt.u32.u64 %0, t; }"
        : "=r"(a) : "l"(p));
    return a;
}
__device__ __forceinline__ void cp_async16(uint32_t saddr, const void* gptr) {
    asm volatile("cp.async.cg.shared.global [%0], [%1], 16;"
                 :: "r"(saddr), "l"(gptr) : "memory");
}
#define CP_COMMIT()  asm volatile("cp.async.commit_group;" ::: "memory")
#define CP_WAIT(n)   asm volatile("cp.async.wait_group %0;" :: "n"(n) : "memory")

__device__ __forceinline__ void ldsm_x4(uint32_t* r, uint32_t addr) {
    asm volatile("ldmatrix.sync.aligned.m8n8.x4.shared.b16 {%0,%1,%2,%3}, [%4];"
                 : "=r"(r[0]), "=r"(r[1]), "=r"(r[2]), "=r"(r[3]) : "r"(addr));
}
__device__ __forceinline__ void ldsm_x2(uint32_t* r, uint32_t addr) {
    asm volatile("ldmatrix.sync.aligned.m8n8.x2.shared.b16 {%0,%1}, [%2];"
                 : "=r"(r[0]), "=r"(r[1]) : "r"(addr));
}
__device__ __forceinline__ void ldsm_x4_trans(uint32_t* r, uint32_t addr) {
    asm volatile("ldmatrix.sync.aligned.m8n8.x4.trans.shared.b16 {%0,%1,%2,%3}, [%4];"
                 : "=r"(r[0]), "=r"(r[1]), "=r"(r[2]), "=r"(r[3]) : "r"(addr));
}
__device__ __forceinline__ void mma_f16(float* c, const uint32_t* a, const uint32_t* b) {
    asm volatile(
        "mma.sync.aligned.m16n8k16.row.col.f32.f16.f16.f32 "
        "{%0,%1,%2,%3}, {%4,%5,%6,%7}, {%8,%9}, {%0,%1,%2,%3};"
        : "+f"(c[0]), "+f"(c[1]), "+f"(c[2]), "+f"(c[3])
        : "r"(a[0]), "r"(a[1]), "r"(a[2]), "r"(a[3]), "r"(b[0]), "r"(b[1]));
}

// FMA-pipe exp (deg-6 2^f poly, rel err ~2e-7).  |x| < 30.
__device__ __forceinline__ float exp_fma(float x) {
    const float r = x * 1.4426950408889634f;
    const float i = rintf(r);
    const float f = r - i;
    float p = 1.5405906e-4f;
    p = fmaf(p, f, 1.3333558e-3f);
    p = fmaf(p, f, 9.6181291e-3f);
    p = fmaf(p, f, 5.5504109e-2f);
    p = fmaf(p, f, 2.4022651e-1f);
    p = fmaf(p, f, 6.9314718e-1f);
    p = fmaf(p, f, 1.0f);
    return p * __int_as_float(((int)i + 127) << 23);
}

// ---------------------------------------------------------------------------
// fp16 split GEMM on mma.sync:  C[M,N] = alpha * (A[M,K] @ op(B))
//  NMMA=2 : A split hi+lo (ah*b + al*b)  — projections
//  NMMA=1 : hi only       (ah*b)        — scores / PV
//  BTRANS=false: B given row-major [N,K]  (op(B)=B^T, plain ldsm)
//  BTRANS=true : B given row-major [K,N]  (op(B)=B, ldsm.trans)
// BM=BN=128, BK=32, 256 threads (2x4 warps), warp tile 64x32.
// 3-stage cp.async ring, one __syncthreads per iter.
// EPI: 2 = fp16 C;
//      4 = fp16 exp(C) + atomic row-sum accumulation into rsum;
//      5 = fp32 C / rsum[row]  (PV with folded softmax normalization)
// ---------------------------------------------------------------------------
constexpr int PITCH   = 80;               // A/B(NT) tile: 64B data + 16B pad
constexpr int TILE_B  = 128 * PITCH;      // 10240 B
constexpr int PITCH_T = 272;              // trans B tile: 256B data + 16B pad
constexpr int TILE_T  = 32 * PITCH_T;     // 8704 B

template <int EPI, int NMMA, bool BTRANS>
__global__ __launch_bounds__(256, 2)
void tc_gemm(const uint16_t* __restrict__ Ah, const uint16_t* __restrict__ Al,
             const uint16_t* __restrict__ Bh,
             uint16_t* __restrict__ Ch, float* __restrict__ C,
             float* __restrict__ rsum,
             int M, int N, int K,
             long long sA, long long sB, long long sC, float alpha)
{
    constexpr int ATILES  = NMMA;                     // 1 or 2
    constexpr int BTILE   = BTRANS ? TILE_T : TILE_B;
    constexpr int BOFF    = ATILES * TILE_B;
    constexpr int STAGE_B = BOFF + BTILE;

    extern __shared__ __align__(128) char smem[];
    const uint32_t sb = smem_u32(smem);
    const int tid  = threadIdx.x;
    const int wid  = tid >> 5;
    const int lane = tid & 31;
    const int z = blockIdx.z;
    Ah += z * sA;  Bh += z * sB;
    if (NMMA == 2) Al += z * sA;
    if (EPI == 4) { Ch += z * sC;  rsum += z * M; }
    if (EPI == 5) { C  += z * sC;  rsum += z * M; }

    const long long bm = (long long)blockIdx.y * 128;
    const long long bn = (long long)blockIdx.x * 128;

    const uint16_t* aSrc[2];
    aSrc[0] = Ah + bm * K;
    aSrc[1] = (NMMA == 2) ? (Al + bm * K) : aSrc[0];
    // BTRANS: B is [K,N] row-major; tile = rows k0..k0+31, cols bn..bn+127
    const uint16_t* bSrc = BTRANS ? (Bh + bn) : (Bh + bn * K);

    auto issue_load = [&](int it, int stg) {
        const uint32_t stage = sb + stg * STAGE_B;
        const int k0 = it * 32;
#pragma unroll
        for (int t = 0; t < ATILES; ++t) {
            const uint16_t* src = aSrc[t] + k0;
#pragma unroll
            for (int c = 0; c < 2; ++c) {
                const int chunk = tid + c * 256;        // 0..511
                const int row = chunk >> 2;
                const int c4  = chunk & 3;
                cp_async16(stage + t * TILE_B + row * PITCH + c4 * 16,
                           src + (long long)row * K + c4 * 8);
            }
        }
        if (BTRANS) {
            // 32 rows x 256B = 512 chunks
#pragma unroll
            for (int c = 0; c < 2; ++c) {
                const int chunk = tid + c * 256;
                const int row = chunk >> 4;             // 0..31
                const int sub = chunk & 15;
                cp_async16(stage + BOFF + row * PITCH_T + sub * 16,
                           bSrc + (long long)(k0 + row) * N + sub * 8);
            }
        } else {
            const uint16_t* src = bSrc + k0;
#pragma unroll
            for (int c = 0; c < 2; ++c) {
                const int chunk = tid + c * 256;
                const int row = chunk >> 2;
                const int c4  = chunk & 3;
                cp_async16(stage + BOFF + row * PITCH + c4 * 16,
                           src + (long long)row * K + c4 * 8);
            }
        }
    };

    const int warpM = wid >> 2;        // 0..1  (64 rows each)
    const int warpN = wid & 3;         // 0..3  (32 cols each)
    const int aRow = warpM * 64 + (lane & 15);
    const int aOff = (lane >> 4) * 16;
    const int bRow = warpN * 32 + (lane & 7);          // non-trans
    const int bOff = ((lane >> 3) & 1) * 16;
    // trans: lane -> (k row within 16-step, n-chunk)
    const int tRow = lane & 15;
    const int tOff = warpN * 64 + (lane >> 4) * 16;    // col bytes

    float acc[4][4][4];
#pragma unroll
    for (int mi = 0; mi < 4; ++mi)
#pragma unroll
        for (int ni = 0; ni < 4; ++ni)
#pragma unroll
            for (int q = 0; q < 4; ++q) acc[mi][ni][q] = 0.f;

    const int niter = K / 32;
    issue_load(0, 0); CP_COMMIT();
    issue_load(1, 1); CP_COMMIT();

    for (int it = 0; it < niter; ++it) {
        const int stg = it - (it / 3) * 3;
        CP_WAIT(1);
        __syncthreads();
        {
            const int nx = it + 2;
            if (nx < niter) issue_load(nx, nx - (nx / 3) * 3);
            CP_COMMIT();
        }

        const uint32_t stage  = sb + stg * STAGE_B;
        const uint32_t aBaseH = stage + aRow * PITCH + aOff;
        const uint32_t aBaseL = stage + TILE_B + aRow * PITCH + aOff;

#pragma unroll
        for (int ks = 0; ks < 2; ++ks) {
            uint32_t ah[4][4], b[4][2];
#pragma unroll
            for (int mi = 0; mi < 4; ++mi)
                ldsm_x4(ah[mi], aBaseH + mi * (16 * PITCH) + ks * 32);
            if (BTRANS) {
                const uint32_t bT = stage + BOFF + (ks * 16 + tRow) * PITCH_T + tOff;
                uint32_t t4[4];
                ldsm_x4_trans(t4, bT);
                b[0][0] = t4[0]; b[0][1] = t4[1]; b[1][0] = t4[2]; b[1][1] = t4[3];
                ldsm_x4_trans(t4, bT + 32);
                b[2][0] = t4[0]; b[2][1] = t4[1]; b[3][0] = t4[2]; b[3][1] = t4[3];
            } else {
                const uint32_t bB = stage + BOFF + bRow * PITCH + bOff;
#pragma unroll
                for (int ni = 0; ni < 4; ++ni)
                    ldsm_x2(b[ni], bB + ni * (8 * PITCH) + ks * 32);
            }
#pragma unroll
            for (int mi = 0; mi < 4; ++mi)
#pragma unroll
                for (int ni = 0; ni < 4; ++ni)
                    mma_f16(acc[mi][ni], ah[mi], b[ni]);
            if (NMMA == 2) {
                uint32_t al[4][4];
#pragma unroll
                for (int mi = 0; mi < 4; ++mi)
                    ldsm_x4(al[mi], aBaseL + mi * (16 * PITCH) + ks * 32);
#pragma unroll
                for (int mi = 0; mi < 4; ++mi)
#pragma unroll
                    for (int ni = 0; ni < 4; ++ni)
                        mma_f16(acc[mi][ni], al[mi], b[ni]);
            }
        }
        __syncthreads();
    }

    // ---- epilogue ----
#pragma unroll
    for (int mi = 0; mi < 4; ++mi) {
#pragma unroll
        for (int h = 0; h < 2; ++h) {
            const long long row = bm + warpM * 64 + (lane >> 2) + mi * 16 + h * 8;
            float rs = 0.f, inv = 0.f;
            if (EPI == 5) inv = 1.f / rsum[row];
#pragma unroll
            for (int ni = 0; ni < 4; ++ni) {
                const int col = (int)bn + warpN * 32 + (lane & 3) * 2 + ni * 8;
                const float f0 = acc[mi][ni][2 * h]     * alpha;
                const float f1 = acc[mi][ni][2 * h + 1] * alpha;
                if (EPI == 2) {
                    __half2 v; v.x = __float2half_rn(f0); v.y = __float2half_rn(f1);
                    *reinterpret_cast<__half2*>(Ch + row * N + col) = v;
                } else if (EPI == 4) {
                    const float e0 = __expf(f0);       // MUFU pipe
                    const float e1 = exp_fma(f1);      // FMA pipe
                    rs += e0 + e1;
                    __half2 v; v.x = __float2half_rn(e0); v.y = __float2half_rn(e1);
                    *reinterpret_cast<__half2*>(Ch + row * N + col) = v;
                } else {
                    float2 v; v.x = f0 * inv; v.y = f1 * inv;
                    *reinterpret_cast<float2*>(C + row * N + col) = v;
                }
            }
            if (EPI == 4) {
                rs += __shfl_xor_sync(0xffffffffu, rs, 1);
                rs += __shfl_xor_sync(0xffffffffu, rs, 2);
                if ((lane & 3) == 0) atomicAdd(rsum + row, rs);
            }
        }
    }
}

// ---------------------------------------------------------------------------
// fp32 -> fp16 hi/lo split (elementwise, float4 vectorized)
// ---------------------------------------------------------------------------
__global__ __launch_bounds__(256)
void split_kernel(const float* __restrict__ in,
                  uint16_t* __restrict__ hi, uint16_t* __restrict__ lo, int n4)
{
    const int i = blockIdx.x * blockDim.x + threadIdx.x;
    if (i >= n4) return;
    float4 v = *reinterpret_cast<const float4*>(in + 4 * (long long)i);
    float f[4] = { v.x, v.y, v.z, v.w };
    __half h[4], l[4];
#pragma unroll
    for (int q = 0; q < 4; ++q) {
        h[q] = __float2half_rn(f[q]);
        l[q] = __float2half_rn(f[q] - __half2float(h[q]));
    }
    __half2 h01, h23, l01, l23;
    h01.x = h[0]; h01.y = h[1]; h23.x = h[2]; h23.y = h[3];
    l01.x = l[0]; l01.y = l[1]; l23.x = l[2]; l23.y = l[3];
    *reinterpret_cast<__half2*>(hi + 4 * (long long)i)     = h01;
    *reinterpret_cast<__half2*>(hi + 4 * (long long)i + 2) = h23;
    *reinterpret_cast<__half2*>(lo + 4 * (long long)i)     = l01;
    *reinterpret_cast<__half2*>(lo + 4 * (long long)i + 2) = l23;
}

// ---------------------------------------------------------------------------
// W[i][o] -> W^T[o][i] as fp16.  512x512.
// ---------------------------------------------------------------------------
__global__ __launch_bounds__(256)
void wtrans_f16(const float* __restrict__ W, uint16_t* __restrict__ Th)
{
    __shared__ float t[32][33];
    const int bx = blockIdx.x * 32;   // o
    const int by = blockIdx.y * 32;   // i
    const int tx = threadIdx.x, ty = threadIdx.y;   // 32 x 8
#pragma unroll
    for (int r = ty; r < 32; r += 8)
        t[r][tx] = W[(by + r) * DIM + bx + tx];
    __syncthreads();
#pragma unroll
    for (int r = ty; r < 32; r += 8)
        reinterpret_cast<__half*>(Th)[(bx + r) * DIM + by + tx] =
            __float2half_rn(t[tx][r]);
}

// ---------------------------------------------------------------------------
__global__ __launch_bounds__(256)
void zero_rsum(float* __restrict__ rsum)
{
    rsum[blockIdx.x * 256 + threadIdx.x] = 0.f;
}

// ---------------------------------------------------------------------------
extern "C" void kernel_launch(void* const* d_in, const int* in_sizes, int n_in,
                              void* d_out, int out_size)
{
    const float* x  = (const float*)d_in[0];
    const float* Wq = (const float*)d_in[1];
    const float* Wk = (const float*)d_in[2];
    const float* Wv = (const float*)d_in[3];
    float* out = (float*)d_out;

    uint16_t *xh, *xl, *Wqh, *Wkh, *Wvh, *Qh, *Kh, *Vh, *Ph;
    float* rsum;
    cudaGetSymbolAddress((void**)&xh, g_xh);   cudaGetSymbolAddress((void**)&xl, g_xl);
    cudaGetSymbolAddress((void**)&Wqh, g_Wqh);
    cudaGetSymbolAddress((void**)&Wkh, g_Wkh);
    cudaGetSymbolAddress((void**)&Wvh, g_Wvh);
    cudaGetSymbolAddress((void**)&Qh, g_Qh);
    cudaGetSymbolAddress((void**)&Kh, g_Kh);
    cudaGetSymbolAddress((void**)&Vh, g_Vh);
    cudaGetSymbolAddress((void**)&Ph, g_Ph);
    cudaGetSymbolAddress((void**)&rsum, g_RSum);

    constexpr int SMP = 3 * (2 * TILE_B + TILE_B);   // 92160 projection (NT A=2 + B)
    constexpr int SMS = 3 * (TILE_B + TILE_B);       // 61440 scores
    constexpr int SMV = 3 * (TILE_B + TILE_T);       // 56832 PV (trans B)
    cudaFuncSetAttribute(tc_gemm<2, 2, false>, cudaFuncAttributeMaxDynamicSharedMemorySize, SMP);
    cudaFuncSetAttribute(tc_gemm<4, 1, false>, cudaFuncAttributeMaxDynamicSharedMemorySize, SMS);
    cudaFuncSetAttribute(tc_gemm<5, 1, true>,  cudaFuncAttributeMaxDynamicSharedMemorySize, SMV);

    // 1. prep: split x to fp16 hi/lo, transpose W to fp16, zero row sums
    split_kernel<<<(MTOT * DIM / 4 + 255) / 256, 256>>>(x, xh, xl, MTOT * DIM / 4);
    wtrans_f16<<<dim3(16, 16), dim3(32, 8)>>>(Wq, Wqh);
    wtrans_f16<<<dim3(16, 16), dim3(32, 8)>>>(Wk, Wkh);
    wtrans_f16<<<dim3(16, 16), dim3(32, 8)>>>(Wv, Wvh);
    zero_rsum<<<MTOT / 256, 256>>>(rsum);

    // 2. projections (fp16 2-MMA): Q, K, V all row-major
    dim3 gp(DIM / 128, MTOT / 128, 1);
    tc_gemm<2, 2, false><<<gp, 256, SMP>>>(xh, xl, Wqh, Qh, nullptr, nullptr,
                                           MTOT, DIM, DIM, 0, 0, 0, 1.f);
    tc_gemm<2, 2, false><<<gp, 256, SMP>>>(xh, xl, Wkh, Kh, nullptr, nullptr,
                                           MTOT, DIM, DIM, 0, 0, 0, 1.f);
    tc_gemm<2, 2, false><<<gp, 256, SMP>>>(xh, xl, Wvh, Vh, nullptr, nullptr,
                                           MTOT, DIM, DIM, 0, 0, 0, 1.f);

    // 3. scores (fp16 1-MMA) + fused exp + atomic row sums
    const float scale = 0.044194173824159216f;   // 1/sqrt(512)
    dim3 gs(SEQ / 128, SEQ / 128, BATCH);
    tc_gemm<4, 1, false><<<gs, 256, SMS>>>(Qh, nullptr, Kh, Ph, nullptr, rsum,
                                           SEQ, SEQ, DIM,
                                           (long long)SEQ * DIM, (long long)SEQ * DIM,
                                           (long long)SEQ * SEQ, scale);

    // 4. context (fp16 1-MMA, B=V row-major via ldsm.trans): out = (Ph V) / rsum
    dim3 gv(DIM / 128, SEQ / 128, BATCH);
    tc_gemm<5, 1, true><<<gv, 256, SMV>>>(Ph, nullptr, Vh, nullptr, out, rsum,
                                          SEQ, DIM, SEQ,
                                          (long long)SEQ * SEQ, (long long)SEQ * DIM,
                                          (long long)SEQ * DIM, 1.f);

    (void)in_sizes; (void)n_in; (void)out_size;
}

// round 10
// speedup vs baseline: 1.6852x; 1.0255x over previous
#include <cuda_runtime.h>
#include <cuda_fp16.h>
#include <cstdint>

#define BATCH 2
#define SEQ   4096
#define DIM   512
#define MTOT  (BATCH*SEQ)   // 8192

// ---------------------------------------------------------------------------
// Scratch (device globals; no allocations allowed).  All fp16.
// ---------------------------------------------------------------------------
__device__ __align__(128) uint16_t g_xh [MTOT*DIM], g_xl [MTOT*DIM];
__device__ __align__(128) uint16_t g_Wqh[DIM*DIM];
__device__ __align__(128) uint16_t g_Wkh[DIM*DIM];
__device__ __align__(128) uint16_t g_Wvh[DIM*DIM];
__device__ __align__(128) uint16_t g_Qh [MTOT*DIM];
__device__ __align__(128) uint16_t g_Kh [MTOT*DIM];
__device__ __align__(128) uint16_t g_Vh [MTOT*DIM];                  // row-major [B][SEQ][DIM]
__device__ __align__(128) uint16_t g_Ph [(long long)BATCH*SEQ*SEQ];  // exp(scores)
__device__ __align__(128) float    g_RSum[MTOT];                     // softmax row sums

// ---------------------------------------------------------------------------
// PTX helpers (sm_80-era ISA only)
// ---------------------------------------------------------------------------
__device__ __forceinline__ uint32_t smem_u32(const void* p) {
    uint32_t a;
    asm("{ .reg .u64 t; cvta.to.shared.u64 t, %1; cvt.u32.u64 %0, t; }"
        : "=r"(a) : "l"(p));
    return a;
}
__device__ __forceinline__ void cp_async16(uint32_t saddr, const void* gptr) {
    asm volatile("cp.async.cg.shared.global [%0], [%1], 16;"
                 :: "r"(saddr), "l"(gptr) : "memory");
}
#define CP_COMMIT()  asm volatile("cp.async.commit_group;" ::: "memory")
#define CP_WAIT(n)   asm volatile("cp.async.wait_group %0;" :: "n"(n) : "memory")

__device__ __forceinline__ void ldsm_x4(uint32_t* r, uint32_t addr) {
    asm volatile("ldmatrix.sync.aligned.m8n8.x4.shared.b16 {%0,%1,%2,%3}, [%4];"
                 : "=r"(r[0]), "=r"(r[1]), "=r"(r[2]), "=r"(r[3]) : "r"(addr));
}
__device__ __forceinline__ void ldsm_x2(uint32_t* r, uint32_t addr) {
    asm volatile("ldmatrix.sync.aligned.m8n8.x2.shared.b16 {%0,%1}, [%2];"
                 : "=r"(r[0]), "=r"(r[1]) : "r"(addr));
}
__device__ __forceinline__ void ldsm_x4_trans(uint32_t* r, uint32_t addr) {
    asm volatile("ldmatrix.sync.aligned.m8n8.x4.trans.shared.b16 {%0,%1,%2,%3}, [%4];"
                 : "=r"(r[0]), "=r"(r[1]), "=r"(r[2]), "=r"(r[3]) : "r"(addr));
}
__device__ __forceinline__ void mma_f16(float* c, const uint32_t* a, const uint32_t* b) {
    asm volatile(
        "mma.sync.aligned.m16n8k16.row.col.f32.f16.f16.f32 "
        "{%0,%1,%2,%3}, {%4,%5,%6,%7}, {%8,%9}, {%0,%1,%2,%3};"
        : "+f"(c[0]), "+f"(c[1]), "+f"(c[2]), "+f"(c[3])
        : "r"(a[0]), "r"(a[1]), "r"(a[2]), "r"(a[3]), "r"(b[0]), "r"(b[1]));
}

// ---------------------------------------------------------------------------
// fp16 split GEMM on mma.sync:  C[M,N] = alpha * (A[M,K] @ op(B))
//  NMMA=2 : A split hi+lo (ah*b + al*b)  — projections
//  NMMA=1 : hi only       (ah*b)        — scores / PV
//  BTRANS=false: B given row-major [N,K]  (op(B)=B^T, plain ldsm)
//  BTRANS=true : B given row-major [K,N]  (op(B)=B, ldsm.trans)
// BM=BN=128, BK=32, 256 threads (2x4 warps), warp tile 64x32.
// 3-stage cp.async ring, one __syncthreads per iter.
// EPI: 2 = fp16 C;
//      4 = fp16 2^(C) via ex2.approx.f16x2 (alpha includes log2e)
//          + atomic row-sum accumulation into rsum;
//      5 = fp32 C / rsum[row]  (PV with folded softmax normalization)
// ---------------------------------------------------------------------------
constexpr int PITCH   = 80;               // A/B tile: 64B data + 16B pad
constexpr int TILE_B  = 128 * PITCH;      // 10240 B
constexpr int PITCH_T = 272;              // trans B tile: 256B data + 16B pad
constexpr int TILE_T  = 32 * PITCH_T;     // 8704 B

template <int EPI, int NMMA, bool BTRANS>
__global__ __launch_bounds__(256, 2)
void tc_gemm(const uint16_t* __restrict__ Ah, const uint16_t* __restrict__ Al,
             const uint16_t* __restrict__ Bh,
             uint16_t* __restrict__ Ch, float* __restrict__ C,
             float* __restrict__ rsum,
             int M, int N, int K,
             long long sA, long long sB, long long sC, float alpha)
{
    constexpr int ATILES  = NMMA;                     // 1 or 2
    constexpr int BTILE   = BTRANS ? TILE_T : TILE_B;
    constexpr int BOFF    = ATILES * TILE_B;
    constexpr int STAGE_B = BOFF + BTILE;

    extern __shared__ __align__(128) char smem[];
    const uint32_t sb = smem_u32(smem);
    const int tid  = threadIdx.x;
    const int wid  = tid >> 5;
    const int lane = tid & 31;
    const int z = blockIdx.z;
    Ah += z * sA;  Bh += z * sB;
    if (NMMA == 2) Al += z * sA;
    if (EPI == 4) { Ch += z * sC;  rsum += z * M; }
    if (EPI == 5) { C  += z * sC;  rsum += z * M; }

    const long long bm = (long long)blockIdx.y * 128;
    const long long bn = (long long)blockIdx.x * 128;

    const uint16_t* aSrc[2];
    aSrc[0] = Ah + bm * K;
    aSrc[1] = (NMMA == 2) ? (Al + bm * K) : aSrc[0];
    const uint16_t* bSrc = BTRANS ? (Bh + bn) : (Bh + bn * K);

    auto issue_load = [&](int it, int stg) {
        const uint32_t stage = sb + stg * STAGE_B;
        const int k0 = it * 32;
#pragma unroll
        for (int t = 0; t < ATILES; ++t) {
            const uint16_t* src = aSrc[t] + k0;
#pragma unroll
            for (int c = 0; c < 2; ++c) {
                const int chunk = tid + c * 256;        // 0..511
                const int row = chunk >> 2;
                const int c4  = chunk & 3;
                cp_async16(stage + t * TILE_B + row * PITCH + c4 * 16,
                           src + (long long)row * K + c4 * 8);
            }
        }
        if (BTRANS) {
#pragma unroll
            for (int c = 0; c < 2; ++c) {
                const int chunk = tid + c * 256;
                const int row = chunk >> 4;             // 0..31
                const int sub = chunk & 15;
                cp_async16(stage + BOFF + row * PITCH_T + sub * 16,
                           bSrc + (long long)(k0 + row) * N + sub * 8);
            }
        } else {
            const uint16_t* src = bSrc + k0;
#pragma unroll
            for (int c = 0; c < 2; ++c) {
                const int chunk = tid + c * 256;
                const int row = chunk >> 2;
                const int c4  = chunk & 3;
                cp_async16(stage + BOFF + row * PITCH + c4 * 16,
                           src + (long long)row * K + c4 * 8);
            }
        }
    };

    const int warpM = wid >> 2;        // 0..1  (64 rows each)
    const int warpN = wid & 3;         // 0..3  (32 cols each)
    const int aRow = warpM * 64 + (lane & 15);
    const int aOff = (lane >> 4) * 16;
    const int bRow = warpN * 32 + (lane & 7);          // non-trans
    const int bOff = ((lane >> 3) & 1) * 16;
    const int tRow = lane & 15;                        // trans
    const int tOff = warpN * 64 + (lane >> 4) * 16;

    float acc[4][4][4];
#pragma unroll
    for (int mi = 0; mi < 4; ++mi)
#pragma unroll
        for (int ni = 0; ni < 4; ++ni)
#pragma unroll
            for (int q = 0; q < 4; ++q) acc[mi][ni][q] = 0.f;

    const int niter = K / 32;
    issue_load(0, 0); CP_COMMIT();
    issue_load(1, 1); CP_COMMIT();

    for (int it = 0; it < niter; ++it) {
        const int stg = it - (it / 3) * 3;
        CP_WAIT(1);
        __syncthreads();
        {
            const int nx = it + 2;
            if (nx < niter) issue_load(nx, nx - (nx / 3) * 3);
            CP_COMMIT();
        }

        const uint32_t stage  = sb + stg * STAGE_B;
        const uint32_t aBaseH = stage + aRow * PITCH + aOff;
        const uint32_t aBaseL = stage + TILE_B + aRow * PITCH + aOff;

#pragma unroll
        for (int ks = 0; ks < 2; ++ks) {
            uint32_t ah[4][4], b[4][2];
#pragma unroll
            for (int mi = 0; mi < 4; ++mi)
                ldsm_x4(ah[mi], aBaseH + mi * (16 * PITCH) + ks * 32);
            if (BTRANS) {
                const uint32_t bT = stage + BOFF + (ks * 16 + tRow) * PITCH_T + tOff;
                uint32_t t4[4];
                ldsm_x4_trans(t4, bT);
                b[0][0] = t4[0]; b[0][1] = t4[1]; b[1][0] = t4[2]; b[1][1] = t4[3];
                ldsm_x4_trans(t4, bT + 32);
                b[2][0] = t4[0]; b[2][1] = t4[1]; b[3][0] = t4[2]; b[3][1] = t4[3];
            } else {
                const uint32_t bB = stage + BOFF + bRow * PITCH + bOff;
#pragma unroll
                for (int ni = 0; ni < 4; ++ni)
                    ldsm_x2(b[ni], bB + ni * (8 * PITCH) + ks * 32);
            }
#pragma unroll
            for (int mi = 0; mi < 4; ++mi)
#pragma unroll
                for (int ni = 0; ni < 4; ++ni)
                    mma_f16(acc[mi][ni], ah[mi], b[ni]);
            if (NMMA == 2) {
                uint32_t al[4][4];
#pragma unroll
                for (int mi = 0; mi < 4; ++mi)
                    ldsm_x4(al[mi], aBaseL + mi * (16 * PITCH) + ks * 32);
#pragma unroll
                for (int mi = 0; mi < 4; ++mi)
#pragma unroll
                    for (int ni = 0; ni < 4; ++ni)
                        mma_f16(acc[mi][ni], al[mi], b[ni]);
            }
        }
        __syncthreads();
    }

    // ---- epilogue ----
#pragma unroll
    for (int mi = 0; mi < 4; ++mi) {
#pragma unroll
        for (int h = 0; h < 2; ++h) {
            const long long row = bm + warpM * 64 + (lane >> 2) + mi * 16 + h * 8;
            float rs = 0.f, inv = 0.f;
            if (EPI == 5) inv = 1.f / rsum[row];
#pragma unroll
            for (int ni = 0; ni < 4; ++ni) {
                const int col = (int)bn + warpN * 32 + (lane & 3) * 2 + ni * 8;
                const float f0 = acc[mi][ni][2 * h]     * alpha;
                const float f1 = acc[mi][ni][2 * h + 1] * alpha;
                if (EPI == 2) {
                    __half2 v; v.x = __float2half_rn(f0); v.y = __float2half_rn(f1);
                    *reinterpret_cast<__half2*>(Ch + row * N + col) = v;
                } else if (EPI == 4) {
                    // f = s * log2e (folded into alpha); P = 2^f via f16x2 MUFU
                    uint32_t packed, e2;
                    asm("cvt.rn.f16x2.f32 %0, %1, %2;" : "=r"(packed) : "f"(f1), "f"(f0));
                    asm("ex2.approx.f16x2 %0, %1;" : "=r"(e2) : "r"(packed));
                    const __half2 v = *reinterpret_cast<__half2*>(&e2);
                    const float2 ff = __half22float2(v);
                    rs += ff.x + ff.y;
                    *reinterpret_cast<__half2*>(Ch + row * N + col) = v;
                } else {
                    float2 v; v.x = f0 * inv; v.y = f1 * inv;
                    *reinterpret_cast<float2*>(C + row * N + col) = v;
                }
            }
            if (EPI == 4) {
                rs += __shfl_xor_sync(0xffffffffu, rs, 1);
                rs += __shfl_xor_sync(0xffffffffu, rs, 2);
                if ((lane & 3) == 0) atomicAdd(rsum + row, rs);
            }
        }
    }
}

// ---------------------------------------------------------------------------
// fp32 -> fp16 hi/lo split (elementwise, float4 vectorized)
// ---------------------------------------------------------------------------
__global__ __launch_bounds__(256)
void split_kernel(const float* __restrict__ in,
                  uint16_t* __restrict__ hi, uint16_t* __restrict__ lo, int n4)
{
    const int i = blockIdx.x * blockDim.x + threadIdx.x;
    if (i >= n4) return;
    float4 v = *reinterpret_cast<const float4*>(in + 4 * (long long)i);
    float f[4] = { v.x, v.y, v.z, v.w };
    __half h[4], l[4];
#pragma unroll
    for (int q = 0; q < 4; ++q) {
        h[q] = __float2half_rn(f[q]);
        l[q] = __float2half_rn(f[q] - __half2float(h[q]));
    }
    __half2 h01, h23, l01, l23;
    h01.x = h[0]; h01.y = h[1]; h23.x = h[2]; h23.y = h[3];
    l01.x = l[0]; l01.y = l[1]; l23.x = l[2]; l23.y = l[3];
    *reinterpret_cast<__half2*>(hi + 4 * (long long)i)     = h01;
    *reinterpret_cast<__half2*>(hi + 4 * (long long)i + 2) = h23;
    *reinterpret_cast<__half2*>(lo + 4 * (long long)i)     = l01;
    *reinterpret_cast<__half2*>(lo + 4 * (long long)i + 2) = l23;
}

// ---------------------------------------------------------------------------
// Fused: all three W[i][o] -> W^T[o][i] fp16 transposes (z selects matrix).
// ---------------------------------------------------------------------------
__global__ __launch_bounds__(256)
void wtrans3_f16(const float* __restrict__ Wq, const float* __restrict__ Wk,
                 const float* __restrict__ Wv,
                 uint16_t* __restrict__ Tq, uint16_t* __restrict__ Tk,
                 uint16_t* __restrict__ Tv)
{
    const float* W = (blockIdx.z == 0) ? Wq : (blockIdx.z == 1) ? Wk : Wv;
    uint16_t*    T = (blockIdx.z == 0) ? Tq : (blockIdx.z == 1) ? Tk : Tv;

    __shared__ float t[32][33];
    const int bx = blockIdx.x * 32;   // o
    const int by = blockIdx.y * 32;   // i
    const int tx = threadIdx.x, ty = threadIdx.y;   // 32 x 8
#pragma unroll
    for (int r = ty; r < 32; r += 8)
        t[r][tx] = W[(by + r) * DIM + bx + tx];
    __syncthreads();
#pragma unroll
    for (int r = ty; r < 32; r += 8)
        reinterpret_cast<__half*>(T)[(bx + r) * DIM + by + tx] =
            __float2half_rn(t[tx][r]);
}

// ---------------------------------------------------------------------------
__global__ __launch_bounds__(256)
void zero_rsum(float* __restrict__ rsum)
{
    rsum[blockIdx.x * 256 + threadIdx.x] = 0.f;
}

// ---------------------------------------------------------------------------
extern "C" void kernel_launch(void* const* d_in, const int* in_sizes, int n_in,
                              void* d_out, int out_size)
{
    const float* x  = (const float*)d_in[0];
    const float* Wq = (const float*)d_in[1];
    const float* Wk = (const float*)d_in[2];
    const float* Wv = (const float*)d_in[3];
    float* out = (float*)d_out;

    uint16_t *xh, *xl, *Wqh, *Wkh, *Wvh, *Qh, *Kh, *Vh, *Ph;
    float* rsum;
    cudaGetSymbolAddress((void**)&xh, g_xh);   cudaGetSymbolAddress((void**)&xl, g_xl);
    cudaGetSymbolAddress((void**)&Wqh, g_Wqh);
    cudaGetSymbolAddress((void**)&Wkh, g_Wkh);
    cudaGetSymbolAddress((void**)&Wvh, g_Wvh);
    cudaGetSymbolAddress((void**)&Qh, g_Qh);
    cudaGetSymbolAddress((void**)&Kh, g_Kh);
    cudaGetSymbolAddress((void**)&Vh, g_Vh);
    cudaGetSymbolAddress((void**)&Ph, g_Ph);
    cudaGetSymbolAddress((void**)&rsum, g_RSum);

    constexpr int SMP = 3 * (2 * TILE_B + TILE_B);   // 92160 projection
    constexpr int SMS = 3 * (TILE_B + TILE_B);       // 61440 scores
    constexpr int SMV = 3 * (TILE_B + TILE_T);       // 56832 PV (trans B)
    cudaFuncSetAttribute(tc_gemm<2, 2, false>, cudaFuncAttributeMaxDynamicSharedMemorySize, SMP);
    cudaFuncSetAttribute(tc_gemm<4, 1, false>, cudaFuncAttributeMaxDynamicSharedMemorySize, SMS);
    cudaFuncSetAttribute(tc_gemm<5, 1, true>,  cudaFuncAttributeMaxDynamicSharedMemorySize, SMV);

    // 1. prep: split x to fp16 hi/lo, transpose W to fp16, zero row sums
    split_kernel<<<(MTOT * DIM / 4 + 255) / 256, 256>>>(x, xh, xl, MTOT * DIM / 4);
    wtrans3_f16<<<dim3(16, 16, 3), dim3(32, 8)>>>(Wq, Wk, Wv, Wqh, Wkh, Wvh);
    zero_rsum<<<MTOT / 256, 256>>>(rsum);

    // 2. projections (fp16 2-MMA): Q, K, V all row-major
    dim3 gp(DIM / 128, MTOT / 128, 1);
    tc_gemm<2, 2, false><<<gp, 256, SMP>>>(xh, xl, Wqh, Qh, nullptr, nullptr,
                                           MTOT, DIM, DIM, 0, 0, 0, 1.f);
    tc_gemm<2, 2, false><<<gp, 256, SMP>>>(xh, xl, Wkh, Kh, nullptr, nullptr,
                                           MTOT, DIM, DIM, 0, 0, 0, 1.f);
    tc_gemm<2, 2, false><<<gp, 256, SMP>>>(xh, xl, Wvh, Vh, nullptr, nullptr,
                                           MTOT, DIM, DIM, 0, 0, 0, 1.f);

    // 3. scores (fp16 1-MMA) + fused 2^x exp + atomic row sums
    //    alpha = (1/sqrt(512)) * log2(e)  so epilogue computes 2^f = exp(s/sqrt512)
    const float alpha_s = 0.044194173824159216f * 1.4426950408889634f;
    dim3 gs(SEQ / 128, SEQ / 128, BATCH);
    tc_gemm<4, 1, false><<<gs, 256, SMS>>>(Qh, nullptr, Kh, Ph, nullptr, rsum,
                                           SEQ, SEQ, DIM,
                                           (long long)SEQ * DIM, (long long)SEQ * DIM,
                                           (long long)SEQ * SEQ, alpha_s);

    // 4. context (fp16 1-MMA, B=V row-major via ldsm.trans): out = (Ph V) / rsum
    dim3 gv(DIM / 128, SEQ / 128, BATCH);
    tc_gemm<5, 1, true><<<gv, 256, SMV>>>(Ph, nullptr, Vh, nullptr, out, rsum,
                                          SEQ, DIM, SEQ,
                                          (long long)SEQ * SEQ, (long long)SEQ * DIM,
                                          (long long)SEQ * DIM, 1.f);

    (void)in_sizes; (void)n_in; (void)out_size;
}

// round 12
// speedup vs baseline: 1.7128x; 1.0164x over previous
#include <cuda_runtime.h>
#include <cuda_fp16.h>
#include <cstdint>

#define BATCH 2
#define SEQ   4096
#define DIM   512
#define MTOT  (BATCH*SEQ)   // 8192

// ---------------------------------------------------------------------------
// Scratch (device globals; no allocations allowed).  All fp16.
// ---------------------------------------------------------------------------
__device__ __align__(128) uint16_t g_xh [MTOT*DIM], g_xl [MTOT*DIM];
__device__ __align__(128) uint16_t g_Wqh[DIM*DIM];
__device__ __align__(128) uint16_t g_Wkh[DIM*DIM];
__device__ __align__(128) uint16_t g_Wvh[DIM*DIM];
__device__ __align__(128) uint16_t g_Qh [MTOT*DIM];
__device__ __align__(128) uint16_t g_Kh [MTOT*DIM];
__device__ __align__(128) uint16_t g_Vh [MTOT*DIM];                  // row-major [B][SEQ][DIM]
__device__ __align__(128) uint16_t g_Ph [(long long)BATCH*SEQ*SEQ];  // exp(scores)
__device__ __align__(128) float    g_RSum[MTOT];                     // softmax row sums

// ---------------------------------------------------------------------------
// PTX helpers (sm_80-era ISA only)
// ---------------------------------------------------------------------------
__device__ __forceinline__ uint32_t smem_u32(const void* p) {
    uint32_t a;
    asm("{ .reg .u64 t; cvta.to.shared.u64 t, %1; cvt.u32.u64 %0, t; }"
        : "=r"(a) : "l"(p));
    return a;
}
__device__ __forceinline__ void cp_async16(uint32_t saddr, const void* gptr) {
    asm volatile("cp.async.cg.shared.global [%0], [%1], 16;"
                 :: "r"(saddr), "l"(gptr) : "memory");
}
#define CP_COMMIT()  asm volatile("cp.async.commit_group;" ::: "memory")
#define CP_WAIT(n)   asm volatile("cp.async.wait_group %0;" :: "n"(n) : "memory")

__device__ __forceinline__ void ldsm_x4(uint32_t* r, uint32_t addr) {
    asm volatile("ldmatrix.sync.aligned.m8n8.x4.shared.b16 {%0,%1,%2,%3}, [%4];"
                 : "=r"(r[0]), "=r"(r[1]), "=r"(r[2]), "=r"(r[3]) : "r"(addr));
}
__device__ __forceinline__ void ldsm_x2(uint32_t* r, uint32_t addr) {
    asm volatile("ldmatrix.sync.aligned.m8n8.x2.shared.b16 {%0,%1}, [%2];"
                 : "=r"(r[0]), "=r"(r[1]) : "r"(addr));
}
__device__ __forceinline__ void ldsm_x4_trans(uint32_t* r, uint32_t addr) {
    asm volatile("ldmatrix.sync.aligned.m8n8.x4.trans.shared.b16 {%0,%1,%2,%3}, [%4];"
                 : "=r"(r[0]), "=r"(r[1]), "=r"(r[2]), "=r"(r[3]) : "r"(addr));
}
__device__ __forceinline__ void mma_f16(float* c, const uint32_t* a, const uint32_t* b) {
    asm volatile(
        "mma.sync.aligned.m16n8k16.row.col.f32.f16.f16.f32 "
        "{%0,%1,%2,%3}, {%4,%5,%6,%7}, {%8,%9}, {%0,%1,%2,%3};"
        : "+f"(c[0]), "+f"(c[1]), "+f"(c[2]), "+f"(c[3])
        : "r"(a[0]), "r"(a[1]), "r"(a[2]), "r"(a[3]), "r"(b[0]), "r"(b[1]));
}

// ---------------------------------------------------------------------------
// fp16 split GEMM on mma.sync:  C[M,N] = alpha * (A[M,K] @ op(B))
//  NMMA=2 : A split hi+lo (ah*b + al*b)  — projections
//  NMMA=1 : hi only       (ah*b)        — scores / PV
//  BTRANS=false: B given row-major [N,K]  (op(B)=B^T, plain ldsm)
//  BTRANS=true : B given row-major [K,N]  (op(B)=B, ldsm.trans)
//  FUSEZ=true  : blockIdx.z selects (B, C) from {Bh,Bh2,Bh3}/{Ch,Ch2,Ch3}
//                (fused Q/K/V projections); z does NOT offset A.
// BM=BN=128, BK=32, 256 threads (2x4 warps), warp tile 64x32.
// 3-stage cp.async ring, one __syncthreads per iter.
// EPI: 2 = fp16 C;
//      4 = fp16 2^(C) via ex2.approx.f16x2 (alpha includes log2e)
//          + atomic row-sum accumulation into rsum;
//      5 = fp32 C / rsum[row]  (PV with folded softmax normalization)
// ---------------------------------------------------------------------------
constexpr int PITCH   = 80;               // A/B tile: 64B data + 16B pad
constexpr int TILE_B  = 128 * PITCH;      // 10240 B
constexpr int PITCH_T = 272;              // trans B tile: 256B data + 16B pad
constexpr int TILE_T  = 32 * PITCH_T;     // 8704 B

template <int EPI, int NMMA, bool BTRANS, bool FUSEZ>
__global__ __launch_bounds__(256, 2)
void tc_gemm(const uint16_t* __restrict__ Ah, const uint16_t* __restrict__ Al,
             const uint16_t* __restrict__ Bh,
             const uint16_t* __restrict__ Bh2, const uint16_t* __restrict__ Bh3,
             uint16_t* __restrict__ Ch,
             uint16_t* __restrict__ Ch2, uint16_t* __restrict__ Ch3,
             float* __restrict__ C, float* __restrict__ rsum,
             int M, int N, int K,
             long long sA, long long sB, long long sC, float alpha)
{
    constexpr int ATILES  = NMMA;                     // 1 or 2
    constexpr int BTILE   = BTRANS ? TILE_T : TILE_B;
    constexpr int BOFF    = ATILES * TILE_B;
    constexpr int STAGE_B = BOFF + BTILE;

    extern __shared__ __align__(128) char smem[];
    const uint32_t sb = smem_u32(smem);
    const int tid  = threadIdx.x;
    const int wid  = tid >> 5;
    const int lane = tid & 31;
    const int z = blockIdx.z;
    if (FUSEZ) {
        // z selects projection matrix; A is shared
        Bh = (z == 0) ? Bh : (z == 1) ? Bh2 : Bh3;
        Ch = (z == 0) ? Ch : (z == 1) ? Ch2 : Ch3;
    } else {
        Ah += z * sA;  Bh += z * sB;
        if (NMMA == 2) Al += z * sA;
        if (EPI == 4) { Ch += z * sC;  rsum += z * M; }
        if (EPI == 5) { C  += z * sC;  rsum += z * M; }
    }

    const long long bm = (long long)blockIdx.y * 128;
    const long long bn = (long long)blockIdx.x * 128;

    const uint16_t* aSrc[2];
    aSrc[0] = Ah + bm * K;
    aSrc[1] = (NMMA == 2) ? (Al + bm * K) : aSrc[0];
    const uint16_t* bSrc = BTRANS ? (Bh + bn) : (Bh + bn * K);

    auto issue_load = [&](int it, int stg) {
        const uint32_t stage = sb + stg * STAGE_B;
        const int k0 = it * 32;
#pragma unroll
        for (int t = 0; t < ATILES; ++t) {
            const uint16_t* src = aSrc[t] + k0;
#pragma unroll
            for (int c = 0; c < 2; ++c) {
                const int chunk = tid + c * 256;        // 0..511
                const int row = chunk >> 2;
                const int c4  = chunk & 3;
                cp_async16(stage + t * TILE_B + row * PITCH + c4 * 16,
                           src + (long long)row * K + c4 * 8);
            }
        }
        if (BTRANS) {
#pragma unroll
            for (int c = 0; c < 2; ++c) {
                const int chunk = tid + c * 256;
                const int row = chunk >> 4;             // 0..31
                const int sub = chunk & 15;
                cp_async16(stage + BOFF + row * PITCH_T + sub * 16,
                           bSrc + (long long)(k0 + row) * N + sub * 8);
            }
        } else {
            const uint16_t* src = bSrc + k0;
#pragma unroll
            for (int c = 0; c < 2; ++c) {
                const int chunk = tid + c * 256;
                const int row = chunk >> 2;
                const int c4  = chunk & 3;
                cp_async16(stage + BOFF + row * PITCH + c4 * 16,
                           src + (long long)row * K + c4 * 8);
            }
        }
    };

    const int warpM = wid >> 2;        // 0..1  (64 rows each)
    const int warpN = wid & 3;         // 0..3  (32 cols each)
    const int aRow = warpM * 64 + (lane & 15);
    const int aOff = (lane >> 4) * 16;
    const int bRow = warpN * 32 + (lane & 7);          // non-trans
    const int bOff = ((lane >> 3) & 1) * 16;
    const int tRow = lane & 15;                        // trans
    const int tOff = warpN * 64 + (lane >> 4) * 16;

    float acc[4][4][4];
#pragma unroll
    for (int mi = 0; mi < 4; ++mi)
#pragma unroll
        for (int ni = 0; ni < 4; ++ni)
#pragma unroll
            for (int q = 0; q < 4; ++q) acc[mi][ni][q] = 0.f;

    const int niter = K / 32;
    issue_load(0, 0); CP_COMMIT();
    issue_load(1, 1); CP_COMMIT();

    for (int it = 0; it < niter; ++it) {
        const int stg = it - (it / 3) * 3;
        CP_WAIT(1);
        __syncthreads();
        {
            const int nx = it + 2;
            if (nx < niter) issue_load(nx, nx - (nx / 3) * 3);
            CP_COMMIT();
        }

        const uint32_t stage  = sb + stg * STAGE_B;
        const uint32_t aBaseH = stage + aRow * PITCH + aOff;
        const uint32_t aBaseL = stage + TILE_B + aRow * PITCH + aOff;

#pragma unroll
        for (int ks = 0; ks < 2; ++ks) {
            uint32_t ah[4][4], b[4][2];
#pragma unroll
            for (int mi = 0; mi < 4; ++mi)
                ldsm_x4(ah[mi], aBaseH + mi * (16 * PITCH) + ks * 32);
            if (BTRANS) {
                const uint32_t bT = stage + BOFF + (ks * 16 + tRow) * PITCH_T + tOff;
                uint32_t t4[4];
                ldsm_x4_trans(t4, bT);
                b[0][0] = t4[0]; b[0][1] = t4[1]; b[1][0] = t4[2]; b[1][1] = t4[3];
                ldsm_x4_trans(t4, bT + 32);
                b[2][0] = t4[0]; b[2][1] = t4[1]; b[3][0] = t4[2]; b[3][1] = t4[3];
            } else {
                const uint32_t bB = stage + BOFF + bRow * PITCH + bOff;
#pragma unroll
                for (int ni = 0; ni < 4; ++ni)
                    ldsm_x2(b[ni], bB + ni * (8 * PITCH) + ks * 32);
            }
#pragma unroll
            for (int mi = 0; mi < 4; ++mi)
#pragma unroll
                for (int ni = 0; ni < 4; ++ni)
                    mma_f16(acc[mi][ni], ah[mi], b[ni]);
            if (NMMA == 2) {
                uint32_t al[4][4];
#pragma unroll
                for (int mi = 0; mi < 4; ++mi)
                    ldsm_x4(al[mi], aBaseL + mi * (16 * PITCH) + ks * 32);
#pragma unroll
                for (int mi = 0; mi < 4; ++mi)
#pragma unroll
                    for (int ni = 0; ni < 4; ++ni)
                        mma_f16(acc[mi][ni], al[mi], b[ni]);
            }
        }
        __syncthreads();
    }

    // ---- epilogue ----
#pragma unroll
    for (int mi = 0; mi < 4; ++mi) {
#pragma unroll
        for (int h = 0; h < 2; ++h) {
            const long long row = bm + warpM * 64 + (lane >> 2) + mi * 16 + h * 8;
            float rs = 0.f, inv = 0.f;
            if (EPI == 5) inv = 1.f / rsum[row];
#pragma unroll
            for (int ni = 0; ni < 4; ++ni) {
                const int col = (int)bn + warpN * 32 + (lane & 3) * 2 + ni * 8;
                const float f0 = acc[mi][ni][2 * h]     * alpha;
                const float f1 = acc[mi][ni][2 * h + 1] * alpha;
                if (EPI == 2) {
                    __half2 v; v.x = __float2half_rn(f0); v.y = __float2half_rn(f1);
                    *reinterpret_cast<__half2*>(Ch + row * N + col) = v;
                } else if (EPI == 4) {
                    // f = s * log2e (folded into alpha); P = 2^f via f16x2 MUFU
                    uint32_t packed, e2;
                    asm("cvt.rn.f16x2.f32 %0, %1, %2;" : "=r"(packed) : "f"(f1), "f"(f0));
                    asm("ex2.approx.f16x2 %0, %1;" : "=r"(e2) : "r"(packed));
                    const __half2 v = *reinterpret_cast<__half2*>(&e2);
                    const float2 ff = __half22float2(v);
                    rs += ff.x + ff.y;
                    *reinterpret_cast<__half2*>(Ch + row * N + col) = v;
                } else {
                    float2 v; v.x = f0 * inv; v.y = f1 * inv;
                    *reinterpret_cast<float2*>(C + row * N + col) = v;
                }
            }
            if (EPI == 4) {
                rs += __shfl_xor_sync(0xffffffffu, rs, 1);
                rs += __shfl_xor_sync(0xffffffffu, rs, 2);
                if ((lane & 3) == 0) atomicAdd(rsum + row, rs);
            }
        }
    }
}

// ---------------------------------------------------------------------------
// fp32 -> fp16 hi/lo split (elementwise, float4 vectorized)
// ---------------------------------------------------------------------------
__global__ __launch_bounds__(256)
void split_kernel(const float* __restrict__ in,
                  uint16_t* __restrict__ hi, uint16_t* __restrict__ lo, int n4)
{
    const int i = blockIdx.x * blockDim.x + threadIdx.x;
    if (i >= n4) return;
    float4 v = *reinterpret_cast<const float4*>(in + 4 * (long long)i);
    float f[4] = { v.x, v.y, v.z, v.w };
    __half h[4], l[4];
#pragma unroll
    for (int q = 0; q < 4; ++q) {
        h[q] = __float2half_rn(f[q]);
        l[q] = __float2half_rn(f[q] - __half2float(h[q]));
    }
    __half2 h01, h23, l01, l23;
    h01.x = h[0]; h01.y = h[1]; h23.x = h[2]; h23.y = h[3];
    l01.x = l[0]; l01.y = l[1]; l23.x = l[2]; l23.y = l[3];
    *reinterpret_cast<__half2*>(hi + 4 * (long long)i)     = h01;
    *reinterpret_cast<__half2*>(hi + 4 * (long long)i + 2) = h23;
    *reinterpret_cast<__half2*>(lo + 4 * (long long)i)     = l01;
    *reinterpret_cast<__half2*>(lo + 4 * (long long)i + 2) = l23;
}

// ---------------------------------------------------------------------------
// Fused: all three W[i][o] -> W^T[o][i] fp16 transposes (z selects matrix).
// ---------------------------------------------------------------------------
__global__ __launch_bounds__(256)
void wtrans3_f16(const float* __restrict__ Wq, const float* __restrict__ Wk,
                 const float* __restrict__ Wv,
                 uint16_t* __restrict__ Tq, uint16_t* __restrict__ Tk,
                 uint16_t* __restrict__ Tv)
{
    const float* W = (blockIdx.z == 0) ? Wq : (blockIdx.z == 1) ? Wk : Wv;
    uint16_t*    T = (blockIdx.z == 0) ? Tq : (blockIdx.z == 1) ? Tk : Tv;

    __shared__ float t[32][33];
    const int bx = blockIdx.x * 32;   // o
    const int by = blockIdx.y * 32;   // i
    const int tx = threadIdx.x, ty = threadIdx.y;   // 32 x 8
#pragma unroll
    for (int r = ty; r < 32; r += 8)
        t[r][tx] = W[(by + r) * DIM + bx + tx];
    __syncthreads();
#pragma unroll
    for (int r = ty; r < 32; r += 8)
        reinterpret_cast<__half*>(T)[(bx + r) * DIM + by + tx] =
            __float2half_rn(t[tx][r]);
}

// ---------------------------------------------------------------------------
__global__ __launch_bounds__(256)
void zero_rsum(float* __restrict__ rsum)
{
    rsum[blockIdx.x * 256 + threadIdx.x] = 0.f;
}

// ---------------------------------------------------------------------------
extern "C" void kernel_launch(void* const* d_in, const int* in_sizes, int n_in,
                              void* d_out, int out_size)
{
    const float* x  = (const float*)d_in[0];
    const float* Wq = (const float*)d_in[1];
    const float* Wk = (const float*)d_in[2];
    const float* Wv = (const float*)d_in[3];
    float* out = (float*)d_out;

    uint16_t *xh, *xl, *Wqh, *Wkh, *Wvh, *Qh, *Kh, *Vh, *Ph;
    float* rsum;
    cudaGetSymbolAddress((void**)&xh, g_xh);   cudaGetSymbolAddress((void**)&xl, g_xl);
    cudaGetSymbolAddress((void**)&Wqh, g_Wqh);
    cudaGetSymbolAddress((void**)&Wkh, g_Wkh);
    cudaGetSymbolAddress((void**)&Wvh, g_Wvh);
    cudaGetSymbolAddress((void**)&Qh, g_Qh);
    cudaGetSymbolAddress((void**)&Kh, g_Kh);
    cudaGetSymbolAddress((void**)&Vh, g_Vh);
    cudaGetSymbolAddress((void**)&Ph, g_Ph);
    cudaGetSymbolAddress((void**)&rsum, g_RSum);

    constexpr int SMP = 3 * (2 * TILE_B + TILE_B);   // 92160 projection
    constexpr int SMS = 3 * (TILE_B + TILE_B);       // 61440 scores
    constexpr int SMV = 3 * (TILE_B + TILE_T);       // 56832 PV (trans B)
    cudaFuncSetAttribute(tc_gemm<2, 2, false, true>,
                         cudaFuncAttributeMaxDynamicSharedMemorySize, SMP);
    cudaFuncSetAttribute(tc_gemm<4, 1, false, false>,
                         cudaFuncAttributeMaxDynamicSharedMemorySize, SMS);
    cudaFuncSetAttribute(tc_gemm<5, 1, true, false>,
                         cudaFuncAttributeMaxDynamicSharedMemorySize, SMV);

    // 1. prep: split x to fp16 hi/lo, transpose W to fp16, zero row sums
    split_kernel<<<(MTOT * DIM / 4 + 255) / 256, 256>>>(x, xh, xl, MTOT * DIM / 4);
    wtrans3_f16<<<dim3(16, 16, 3), dim3(32, 8)>>>(Wq, Wk, Wv, Wqh, Wkh, Wvh);
    zero_rsum<<<MTOT / 256, 256>>>(rsum);

    // 2. fused projections (fp16 2-MMA): one launch, z selects Q/K/V
    dim3 gp(DIM / 128, MTOT / 128, 3);
    tc_gemm<2, 2, false, true><<<gp, 256, SMP>>>(
        xh, xl, Wqh, Wkh, Wvh, Qh, Kh, Vh, nullptr, nullptr,
        MTOT, DIM, DIM, 0, 0, 0, 1.f);

    // 3. scores (fp16 1-MMA) + fused 2^x exp + atomic row sums
    //    alpha = (1/sqrt(512)) * log2(e)  so epilogue computes 2^f = exp(s/sqrt512)
    const float alpha_s = 0.044194173824159216f * 1.4426950408889634f;
    dim3 gs(SEQ / 128, SEQ / 128, BATCH);
    tc_gemm<4, 1, false, false><<<gs, 256, SMS>>>(
        Qh, nullptr, Kh, nullptr, nullptr, Ph, nullptr, nullptr, nullptr, rsum,
        SEQ, SEQ, DIM,
        (long long)SEQ * DIM, (long long)SEQ * DIM, (long long)SEQ * SEQ, alpha_s);

    // 4. context (fp16 1-MMA, B=V row-major via ldsm.trans): out = (Ph V) / rsum
    dim3 gv(DIM / 128, SEQ / 128, BATCH);
    tc_gemm<5, 1, true, false><<<gv, 256, SMV>>>(
        Ph, nullptr, Vh, nullptr, nullptr, nullptr, nullptr, nullptr, out, rsum,
        SEQ, DIM, SEQ,
        (long long)SEQ * SEQ, (long long)SEQ * DIM, (long long)SEQ * DIM, 1.f);

    (void)in_sizes; (void)n_in; (void)out_size;
}

// round 14
// speedup vs baseline: 1.7856x; 1.0425x over previous
#include <cuda_runtime.h>
#include <cuda_fp16.h>
#include <cstdint>

#define BATCH 2
#define SEQ   4096
#define DIM   512
#define MTOT  (BATCH*SEQ)   // 8192

// ---------------------------------------------------------------------------
// Scratch (device globals; no allocations allowed).  All fp16.
// ---------------------------------------------------------------------------
__device__ __align__(128) uint16_t g_xh [MTOT*DIM], g_xl [MTOT*DIM];
__device__ __align__(128) uint16_t g_Wqh[DIM*DIM];
__device__ __align__(128) uint16_t g_Wkh[DIM*DIM];
__device__ __align__(128) uint16_t g_Wvh[DIM*DIM];
__device__ __align__(128) uint16_t g_Qh [MTOT*DIM];
__device__ __align__(128) uint16_t g_Kh [MTOT*DIM];
__device__ __align__(128) uint16_t g_Vh [MTOT*DIM];                  // row-major [B][SEQ][DIM]
__device__ __align__(128) uint16_t g_Ph [(long long)BATCH*SEQ*SEQ];  // exp(scores)
__device__ __align__(128) float    g_RSum[MTOT];                     // softmax row sums

// ---------------------------------------------------------------------------
// PTX helpers (sm_80-era ISA only)
// ---------------------------------------------------------------------------
__device__ __forceinline__ uint32_t smem_u32(const void* p) {
    uint32_t a;
    asm("{ .reg .u64 t; cvta.to.shared.u64 t, %1; cvt.u32.u64 %0, t; }"
        : "=r"(a) : "l"(p));
    return a;
}
__device__ __forceinline__ void cp_async16(uint32_t saddr, const void* gptr) {
    asm volatile("cp.async.cg.shared.global [%0], [%1], 16;"
                 :: "r"(saddr), "l"(gptr) : "memory");
}
#define CP_COMMIT()  asm volatile("cp.async.commit_group;" ::: "memory")
#define CP_WAIT(n)   asm volatile("cp.async.wait_group %0;" :: "n"(n) : "memory")

__device__ __forceinline__ void ldsm_x4(uint32_t* r, uint32_t addr) {
    asm volatile("ldmatrix.sync.aligned.m8n8.x4.shared.b16 {%0,%1,%2,%3}, [%4];"
                 : "=r"(r[0]), "=r"(r[1]), "=r"(r[2]), "=r"(r[3]) : "r"(addr));
}
__device__ __forceinline__ void ldsm_x2(uint32_t* r, uint32_t addr) {
    asm volatile("ldmatrix.sync.aligned.m8n8.x2.shared.b16 {%0,%1}, [%2];"
                 : "=r"(r[0]), "=r"(r[1]) : "r"(addr));
}
__device__ __forceinline__ void ldsm_x4_trans(uint32_t* r, uint32_t addr) {
    asm volatile("ldmatrix.sync.aligned.m8n8.x4.trans.shared.b16 {%0,%1,%2,%3}, [%4];"
                 : "=r"(r[0]), "=r"(r[1]), "=r"(r[2]), "=r"(r[3]) : "r"(addr));
}
__device__ __forceinline__ void mma_f16(float* c, const uint32_t* a, const uint32_t* b) {
    asm volatile(
        "mma.sync.aligned.m16n8k16.row.col.f32.f16.f16.f32 "
        "{%0,%1,%2,%3}, {%4,%5,%6,%7}, {%8,%9}, {%0,%1,%2,%3};"
        : "+f"(c[0]), "+f"(c[1]), "+f"(c[2]), "+f"(c[3])
        : "r"(a[0]), "r"(a[1]), "r"(a[2]), "r"(a[3]), "r"(b[0]), "r"(b[1]));
}

// ---------------------------------------------------------------------------
// Compile-time tile geometry (template structs: usable in both host & device)
// ---------------------------------------------------------------------------
template <int BKT> struct Geom {
    static constexpr int PITCH  = BKT * 2 + 16;       // row bytes + 16B pad
    static constexpr int TILE_B = 128 * PITCH;
    static constexpr int PITCH_T = 272;               // 256B data + 16B pad
    static constexpr int TILE_T = BKT * PITCH_T;
};

// ---------------------------------------------------------------------------
// fp16 split GEMM on mma.sync:  C[M,N] = alpha * (A[M,K] @ op(B))
//  NMMA=2 : A split hi+lo (ah*b + al*b)  — projections
//  NMMA=1 : hi only       (ah*b)        — scores / PV
//  BTRANS=false: B given row-major [N,K]  (op(B)=B^T, plain ldsm)
//  BTRANS=true : B given row-major [K,N]  (op(B)=B, ldsm.trans)
//  FUSEZ=true  : blockIdx.z selects (B, C) from {Bh,Bh2,Bh3}/{Ch,Ch2,Ch3}
//  BKT: K-slab depth (32 or 64).  One __syncthreads per slab.
// BM=BN=128, 256 threads (2x4 warps), warp tile 64x32, 3-stage cp.async ring.
// EPI: 2 = fp16 C;
//      4 = fp16 2^(C) via ex2.approx.f16x2 (alpha includes log2e)
//          + atomic row-sum accumulation into rsum;
//      5 = fp32 C / rsum[row]  (PV with folded softmax normalization)
// ---------------------------------------------------------------------------
template <int EPI, int NMMA, bool BTRANS, bool FUSEZ, int BKT>
__global__ __launch_bounds__(256, 2)
void tc_gemm(const uint16_t* __restrict__ Ah, const uint16_t* __restrict__ Al,
             const uint16_t* __restrict__ Bh,
             const uint16_t* __restrict__ Bh2, const uint16_t* __restrict__ Bh3,
             uint16_t* __restrict__ Ch,
             uint16_t* __restrict__ Ch2, uint16_t* __restrict__ Ch3,
             float* __restrict__ C, float* __restrict__ rsum,
             int M, int N, int K,
             long long sA, long long sB, long long sC, float alpha)
{
    constexpr int PITCH   = Geom<BKT>::PITCH;
    constexpr int TILE_B  = Geom<BKT>::TILE_B;
    constexpr int PITCH_T = Geom<BKT>::PITCH_T;
    constexpr int ATILES  = NMMA;                     // 1 or 2
    constexpr int BTILE   = BTRANS ? Geom<BKT>::TILE_T : TILE_B;
    constexpr int BOFF    = ATILES * TILE_B;
    constexpr int STAGE_B = BOFF + BTILE;
    constexpr int NKS     = BKT / 16;                 // ks steps per slab
    constexpr int ACH     = BKT / 8;                  // 16B chunks per row

    extern __shared__ __align__(128) char smem[];
    const uint32_t sb = smem_u32(smem);
    const int tid  = threadIdx.x;
    const int wid  = tid >> 5;
    const int lane = tid & 31;
    const int z = blockIdx.z;
    if (FUSEZ) {
        Bh = (z == 0) ? Bh : (z == 1) ? Bh2 : Bh3;
        Ch = (z == 0) ? Ch : (z == 1) ? Ch2 : Ch3;
    } else {
        Ah += z * sA;  Bh += z * sB;
        if (NMMA == 2) Al += z * sA;
        if (EPI == 4) { Ch += z * sC;  rsum += z * M; }
        if (EPI == 5) { C  += z * sC;  rsum += z * M; }
    }

    const long long bm = (long long)blockIdx.y * 128;
    const long long bn = (long long)blockIdx.x * 128;

    const uint16_t* aSrc[2];
    aSrc[0] = Ah + bm * K;
    aSrc[1] = (NMMA == 2) ? (Al + bm * K) : aSrc[0];
    const uint16_t* bSrc = BTRANS ? (Bh + bn) : (Bh + bn * K);

    auto issue_load = [&](int it, int stg) {
        const uint32_t stage = sb + stg * STAGE_B;
        const int k0 = it * BKT;
#pragma unroll
        for (int t = 0; t < ATILES; ++t) {
            const uint16_t* src = aSrc[t] + k0;
#pragma unroll
            for (int c = 0; c < ACH / 2; ++c) {
                const int chunk = tid + c * 256;             // 0..128*ACH-1
                const int row = chunk / ACH;
                const int sub = chunk % ACH;
                cp_async16(stage + t * TILE_B + row * PITCH + sub * 16,
                           src + (long long)row * K + sub * 8);
            }
        }
        if (BTRANS) {
            // BKT rows x 256B = BKT*16 chunks
#pragma unroll
            for (int c = 0; c < BKT / 16; ++c) {
                const int chunk = tid + c * 256;
                const int row = chunk >> 4;                  // 0..BKT-1
                const int sub = chunk & 15;
                cp_async16(stage + BOFF + row * PITCH_T + sub * 16,
                           bSrc + (long long)(k0 + row) * N + sub * 8);
            }
        } else {
            const uint16_t* src = bSrc + k0;
#pragma unroll
            for (int c = 0; c < ACH / 2; ++c) {
                const int chunk = tid + c * 256;
                const int row = chunk / ACH;
                const int sub = chunk % ACH;
                cp_async16(stage + BOFF + row * PITCH + sub * 16,
                           src + (long long)row * K + sub * 8);
            }
        }
    };

    const int warpM = wid >> 2;        // 0..1  (64 rows each)
    const int warpN = wid & 3;         // 0..3  (32 cols each)
    const int aRow = warpM * 64 + (lane & 15);
    const int aOff = (lane >> 4) * 16;
    const int bRow = warpN * 32 + (lane & 7);          // non-trans
    const int bOff = ((lane >> 3) & 1) * 16;
    const int tRow = lane & 15;                        // trans
    const int tOff = warpN * 64 + (lane >> 4) * 16;

    float acc[4][4][4];
#pragma unroll
    for (int mi = 0; mi < 4; ++mi)
#pragma unroll
        for (int ni = 0; ni < 4; ++ni)
#pragma unroll
            for (int q = 0; q < 4; ++q) acc[mi][ni][q] = 0.f;

    const int niter = K / BKT;
    issue_load(0, 0); CP_COMMIT();
    issue_load(1, 1); CP_COMMIT();

    for (int it = 0; it < niter; ++it) {
        const int stg = it - (it / 3) * 3;
        CP_WAIT(1);
        __syncthreads();
        {
            const int nx = it + 2;
            if (nx < niter) issue_load(nx, nx - (nx / 3) * 3);
            CP_COMMIT();
        }

        const uint32_t stage  = sb + stg * STAGE_B;
        const uint32_t aBaseH = stage + aRow * PITCH + aOff;
        const uint32_t aBaseL = stage + TILE_B + aRow * PITCH + aOff;

#pragma unroll
        for (int ks = 0; ks < NKS; ++ks) {
            uint32_t ah[4][4], b[4][2];
#pragma unroll
            for (int mi = 0; mi < 4; ++mi)
                ldsm_x4(ah[mi], aBaseH + mi * (16 * PITCH) + ks * 32);
            if (BTRANS) {
                const uint32_t bT = stage + BOFF + (ks * 16 + tRow) * PITCH_T + tOff;
                uint32_t t4[4];
                ldsm_x4_trans(t4, bT);
                b[0][0] = t4[0]; b[0][1] = t4[1]; b[1][0] = t4[2]; b[1][1] = t4[3];
                ldsm_x4_trans(t4, bT + 32);
                b[2][0] = t4[0]; b[2][1] = t4[1]; b[3][0] = t4[2]; b[3][1] = t4[3];
            } else {
                const uint32_t bB = stage + BOFF + bRow * PITCH + bOff;
#pragma unroll
                for (int ni = 0; ni < 4; ++ni)
                    ldsm_x2(b[ni], bB + ni * (8 * PITCH) + ks * 32);
            }
#pragma unroll
            for (int mi = 0; mi < 4; ++mi)
#pragma unroll
                for (int ni = 0; ni < 4; ++ni)
                    mma_f16(acc[mi][ni], ah[mi], b[ni]);
            if (NMMA == 2) {
                uint32_t al[4][4];
#pragma unroll
                for (int mi = 0; mi < 4; ++mi)
                    ldsm_x4(al[mi], aBaseL + mi * (16 * PITCH) + ks * 32);
#pragma unroll
                for (int mi = 0; mi < 4; ++mi)
#pragma unroll
                    for (int ni = 0; ni < 4; ++ni)
                        mma_f16(acc[mi][ni], al[mi], b[ni]);
            }
        }
        __syncthreads();
    }

    // ---- epilogue ----
#pragma unroll
    for (int mi = 0; mi < 4; ++mi) {
#pragma unroll
        for (int h = 0; h < 2; ++h) {
            const long long row = bm + warpM * 64 + (lane >> 2) + mi * 16 + h * 8;
            float rs = 0.f, inv = 0.f;
            if (EPI == 5) inv = 1.f / rsum[row];
#pragma unroll
            for (int ni = 0; ni < 4; ++ni) {
                const int col = (int)bn + warpN * 32 + (lane & 3) * 2 + ni * 8;
                const float f0 = acc[mi][ni][2 * h]     * alpha;
                const float f1 = acc[mi][ni][2 * h + 1] * alpha;
                if (EPI == 2) {
                    __half2 v; v.x = __float2half_rn(f0); v.y = __float2half_rn(f1);
                    *reinterpret_cast<__half2*>(Ch + row * N + col) = v;
                } else if (EPI == 4) {
                    // f = s * log2e (folded into alpha); P = 2^f via f16x2 MUFU
                    uint32_t packed, e2;
                    asm("cvt.rn.f16x2.f32 %0, %1, %2;" : "=r"(packed) : "f"(f1), "f"(f0));
                    asm("ex2.approx.f16x2 %0, %1;" : "=r"(e2) : "r"(packed));
                    const __half2 v = *reinterpret_cast<__half2*>(&e2);
                    const float2 ff = __half22float2(v);
                    rs += ff.x + ff.y;
                    *reinterpret_cast<__half2*>(Ch + row * N + col) = v;
                } else {
                    float2 v; v.x = f0 * inv; v.y = f1 * inv;
                    *reinterpret_cast<float2*>(C + row * N + col) = v;
                }
            }
            if (EPI == 4) {
                rs += __shfl_xor_sync(0xffffffffu, rs, 1);
                rs += __shfl_xor_sync(0xffffffffu, rs, 2);
                if ((lane & 3) == 0) atomicAdd(rsum + row, rs);
            }
        }
    }
}

// ---------------------------------------------------------------------------
// fp32 -> fp16 hi/lo split (elementwise, float4 vectorized)
// ---------------------------------------------------------------------------
__global__ __launch_bounds__(256)
void split_kernel(const float* __restrict__ in,
                  uint16_t* __restrict__ hi, uint16_t* __restrict__ lo, int n4)
{
    const int i = blockIdx.x * blockDim.x + threadIdx.x;
    if (i >= n4) return;
    float4 v = *reinterpret_cast<const float4*>(in + 4 * (long long)i);
    float f[4] = { v.x, v.y, v.z, v.w };
    __half h[4], l[4];
#pragma unroll
    for (int q = 0; q < 4; ++q) {
        h[q] = __float2half_rn(f[q]);
        l[q] = __float2half_rn(f[q] - __half2float(h[q]));
    }
    __half2 h01, h23, l01, l23;
    h01.x = h[0]; h01.y = h[1]; h23.x = h[2]; h23.y = h[3];
    l01.x = l[0]; l01.y = l[1]; l23.x = l[2]; l23.y = l[3];
    *reinterpret_cast<__half2*>(hi + 4 * (long long)i)     = h01;
    *reinterpret_cast<__half2*>(hi + 4 * (long long)i + 2) = h23;
    *reinterpret_cast<__half2*>(lo + 4 * (long long)i)     = l01;
    *reinterpret_cast<__half2*>(lo + 4 * (long long)i + 2) = l23;
}

// ---------------------------------------------------------------------------
// Fused: all three W[i][o] -> W^T[o][i] fp16 transposes (z selects matrix).
// ---------------------------------------------------------------------------
__global__ __launch_bounds__(256)
void wtrans3_f16(const float* __restrict__ Wq, const float* __restrict__ Wk,
                 const float* __restrict__ Wv,
                 uint16_t* __restrict__ Tq, uint16_t* __restrict__ Tk,
                 uint16_t* __restrict__ Tv)
{
    const float* W = (blockIdx.z == 0) ? Wq : (blockIdx.z == 1) ? Wk : Wv;
    uint16_t*    T = (blockIdx.z == 0) ? Tq : (blockIdx.z == 1) ? Tk : Tv;

    __shared__ float t[32][33];
    const int bx = blockIdx.x * 32;   // o
    const int by = blockIdx.y * 32;   // i
    const int tx = threadIdx.x, ty = threadIdx.y;   // 32 x 8
#pragma unroll
    for (int r = ty; r < 32; r += 8)
        t[r][tx] = W[(by + r) * DIM + bx + tx];
    __syncthreads();
#pragma unroll
    for (int r = ty; r < 32; r += 8)
        reinterpret_cast<__half*>(T)[(bx + r) * DIM + by + tx] =
            __float2half_rn(t[tx][r]);
}

// ---------------------------------------------------------------------------
__global__ __launch_bounds__(256)
void zero_rsum(float* __restrict__ rsum)
{
    rsum[blockIdx.x * 256 + threadIdx.x] = 0.f;
}

// ---------------------------------------------------------------------------
extern "C" void kernel_launch(void* const* d_in, const int* in_sizes, int n_in,
                              void* d_out, int out_size)
{
    const float* x  = (const float*)d_in[0];
    const float* Wq = (const float*)d_in[1];
    const float* Wk = (const float*)d_in[2];
    const float* Wv = (const float*)d_in[3];
    float* out = (float*)d_out;

    uint16_t *xh, *xl, *Wqh, *Wkh, *Wvh, *Qh, *Kh, *Vh, *Ph;
    float* rsum;
    cudaGetSymbolAddress((void**)&xh, g_xh);   cudaGetSymbolAddress((void**)&xl, g_xl);
    cudaGetSymbolAddress((void**)&Wqh, g_Wqh);
    cudaGetSymbolAddress((void**)&Wkh, g_Wkh);
    cudaGetSymbolAddress((void**)&Wvh, g_Wvh);
    cudaGetSymbolAddress((void**)&Qh, g_Qh);
    cudaGetSymbolAddress((void**)&Kh, g_Kh);
    cudaGetSymbolAddress((void**)&Vh, g_Vh);
    cudaGetSymbolAddress((void**)&Ph, g_Ph);
    cudaGetSymbolAddress((void**)&rsum, g_RSum);

    // projections: BK=32, NT=3  -> 3 * 3 * 10240 = 92160
    constexpr int SMP = 3 * 3 * Geom<32>::TILE_B;
    // scores: BK=64, 2 tiles    -> 3 * 2 * 18432 = 110592
    constexpr int SMS = 3 * 2 * Geom<64>::TILE_B;
    // PV: BK=64, A + trans B    -> 3 * (18432 + 17408) = 107520
    constexpr int SMV = 3 * (Geom<64>::TILE_B + Geom<64>::TILE_T);
    cudaFuncSetAttribute(tc_gemm<2, 2, false, true, 32>,
                         cudaFuncAttributeMaxDynamicSharedMemorySize, SMP);
    cudaFuncSetAttribute(tc_gemm<4, 1, false, false, 64>,
                         cudaFuncAttributeMaxDynamicSharedMemorySize, SMS);
    cudaFuncSetAttribute(tc_gemm<5, 1, true, false, 64>,
                         cudaFuncAttributeMaxDynamicSharedMemorySize, SMV);

    // 1. prep: split x to fp16 hi/lo, transpose W to fp16, zero row sums
    split_kernel<<<(MTOT * DIM / 4 + 255) / 256, 256>>>(x, xh, xl, MTOT * DIM / 4);
    wtrans3_f16<<<dim3(16, 16, 3), dim3(32, 8)>>>(Wq, Wk, Wv, Wqh, Wkh, Wvh);
    zero_rsum<<<MTOT / 256, 256>>>(rsum);

    // 2. fused projections (fp16 2-MMA, BK=32): one launch, z selects Q/K/V
    dim3 gp(DIM / 128, MTOT / 128, 3);
    tc_gemm<2, 2, false, true, 32><<<gp, 256, SMP>>>(
        xh, xl, Wqh, Wkh, Wvh, Qh, Kh, Vh, nullptr, nullptr,
        MTOT, DIM, DIM, 0, 0, 0, 1.f);

    // 3. scores (fp16 1-MMA, BK=64) + fused 2^x exp + atomic row sums
    const float alpha_s = 0.044194173824159216f * 1.4426950408889634f;
    dim3 gs(SEQ / 128, SEQ / 128, BATCH);
    tc_gemm<4, 1, false, false, 64><<<gs, 256, SMS>>>(
        Qh, nullptr, Kh, nullptr, nullptr, Ph, nullptr, nullptr, nullptr, rsum,
        SEQ, SEQ, DIM,
        (long long)SEQ * DIM, (long long)SEQ * DIM, (long long)SEQ * SEQ, alpha_s);

    // 4. context (fp16 1-MMA, BK=64, B=V row-major via ldsm.trans)
    dim3 gv(DIM / 128, SEQ / 128, BATCH);
    tc_gemm<5, 1, true, false, 64><<<gv, 256, SMV>>>(
        Ph, nullptr, Vh, nullptr, nullptr, nullptr, nullptr, nullptr, out, rsum,
        SEQ, DIM, SEQ,
        (long long)SEQ * SEQ, (long long)SEQ * DIM, (long long)SEQ * DIM, 1.f);

    (void)in_sizes; (void)n_in; (void)out_size;
}

// round 15
// speedup vs baseline: 2.0277x; 1.1356x over previous
#include <cuda_runtime.h>
#include <cuda_fp16.h>
#include <cstdint>

#define BATCH 2
#define SEQ   4096
#define DIM   512
#define MTOT  (BATCH*SEQ)   // 8192

// ---------------------------------------------------------------------------
// Scratch (device globals; no allocations allowed).  All fp16.
// ---------------------------------------------------------------------------
__device__ __align__(128) uint16_t g_xh [MTOT*DIM];
__device__ __align__(128) uint16_t g_Wqh[DIM*DIM];
__device__ __align__(128) uint16_t g_Wkh[DIM*DIM];
__device__ __align__(128) uint16_t g_Wvh[DIM*DIM];
__device__ __align__(128) uint16_t g_Qh [MTOT*DIM];
__device__ __align__(128) uint16_t g_Kh [MTOT*DIM];
__device__ __align__(128) uint16_t g_Vh [MTOT*DIM];                  // row-major [B][SEQ][DIM]
__device__ __align__(128) uint16_t g_Ph [(long long)BATCH*SEQ*SEQ];  // exp(scores)
__device__ __align__(128) float    g_RSum[MTOT];                     // softmax row sums

// ---------------------------------------------------------------------------
// PTX helpers (sm_80-era ISA only)
// ---------------------------------------------------------------------------
__device__ __forceinline__ uint32_t smem_u32(const void* p) {
    uint32_t a;
    asm("{ .reg .u64 t; cvta.to.shared.u64 t, %1; cvt.u32.u64 %0, t; }"
        : "=r"(a) : "l"(p));
    return a;
}
__device__ __forceinline__ void cp_async16(uint32_t saddr, const void* gptr) {
    asm volatile("cp.async.cg.shared.global [%0], [%1], 16;"
                 :: "r"(saddr), "l"(gptr) : "memory");
}
#define CP_COMMIT()  asm volatile("cp.async.commit_group;" ::: "memory")
#define CP_WAIT(n)   asm volatile("cp.async.wait_group %0;" :: "n"(n) : "memory")

__device__ __forceinline__ void ldsm_x4(uint32_t* r, uint32_t addr) {
    asm volatile("ldmatrix.sync.aligned.m8n8.x4.shared.b16 {%0,%1,%2,%3}, [%4];"
                 : "=r"(r[0]), "=r"(r[1]), "=r"(r[2]), "=r"(r[3]) : "r"(addr));
}
__device__ __forceinline__ void ldsm_x2(uint32_t* r, uint32_t addr) {
    asm volatile("ldmatrix.sync.aligned.m8n8.x2.shared.b16 {%0,%1}, [%2];"
                 : "=r"(r[0]), "=r"(r[1]) : "r"(addr));
}
__device__ __forceinline__ void ldsm_x4_trans(uint32_t* r, uint32_t addr) {
    asm volatile("ldmatrix.sync.aligned.m8n8.x4.trans.shared.b16 {%0,%1,%2,%3}, [%4];"
                 : "=r"(r[0]), "=r"(r[1]), "=r"(r[2]), "=r"(r[3]) : "r"(addr));
}
__device__ __forceinline__ void mma_f16(float* c, const uint32_t* a, const uint32_t* b) {
    asm volatile(
        "mma.sync.aligned.m16n8k16.row.col.f32.f16.f16.f32 "
        "{%0,%1,%2,%3}, {%4,%5,%6,%7}, {%8,%9}, {%0,%1,%2,%3};"
        : "+f"(c[0]), "+f"(c[1]), "+f"(c[2]), "+f"(c[3])
        : "r"(a[0]), "r"(a[1]), "r"(a[2]), "r"(a[3]), "r"(b[0]), "r"(b[1]));
}

// ---------------------------------------------------------------------------
// Compile-time tile geometry
// ---------------------------------------------------------------------------
template <int BKT> struct Geom {
    static constexpr int PITCH  = BKT * 2 + 16;       // row bytes + 16B pad
    static constexpr int TILE_B = 128 * PITCH;
    static constexpr int PITCH_T = 272;               // 256B data + 16B pad
    static constexpr int TILE_T = BKT * PITCH_T;
};

// ---------------------------------------------------------------------------
// fp16 GEMM on mma.sync:  C[M,N] = alpha * (A[M,K] @ op(B))
//  NMMA=2 : A split hi+lo (ah*b + al*b)
//  NMMA=1 : hi only       (ah*b)
//  BTRANS=false: B row-major [N,K] (op(B)=B^T, plain ldsm)
//  BTRANS=true : B row-major [K,N] (op(B)=B, ldsm.trans)
//  FUSEZ=true  : blockIdx.z selects (B, C) from triples (fused Q/K/V proj)
//  BKT: K-slab depth.  One __syncthreads per slab, 3-stage cp.async ring.
// BM=BN=128, 256 threads (2x4 warps), warp tile 64x32.
// EPI: 2 = fp16 C;
//      4 = fp16 2^(C) via ex2.approx.f16x2 (alpha includes log2e)
//          + atomic row-sum accumulation into rsum;
//      5 = fp32 C / rsum[row]  (PV with folded softmax normalization)
// ---------------------------------------------------------------------------
template <int EPI, int NMMA, bool BTRANS, bool FUSEZ, int BKT>
__global__ __launch_bounds__(256, 2)
void tc_gemm(const uint16_t* __restrict__ Ah, const uint16_t* __restrict__ Al,
             const uint16_t* __restrict__ Bh,
             const uint16_t* __restrict__ Bh2, const uint16_t* __restrict__ Bh3,
             uint16_t* __restrict__ Ch,
             uint16_t* __restrict__ Ch2, uint16_t* __restrict__ Ch3,
             float* __restrict__ C, float* __restrict__ rsum,
             int M, int N, int K,
             long long sA, long long sB, long long sC, float alpha)
{
    constexpr int PITCH   = Geom<BKT>::PITCH;
    constexpr int TILE_B  = Geom<BKT>::TILE_B;
    constexpr int PITCH_T = Geom<BKT>::PITCH_T;
    constexpr int ATILES  = NMMA;                     // 1 or 2
    constexpr int BTILE   = BTRANS ? Geom<BKT>::TILE_T : TILE_B;
    constexpr int BOFF    = ATILES * TILE_B;
    constexpr int STAGE_B = BOFF + BTILE;
    constexpr int NKS     = BKT / 16;                 // ks steps per slab
    constexpr int ACH     = BKT / 8;                  // 16B chunks per row

    extern __shared__ __align__(128) char smem[];
    const uint32_t sb = smem_u32(smem);
    const int tid  = threadIdx.x;
    const int wid  = tid >> 5;
    const int lane = tid & 31;
    const int z = blockIdx.z;
    if (FUSEZ) {
        Bh = (z == 0) ? Bh : (z == 1) ? Bh2 : Bh3;
        Ch = (z == 0) ? Ch : (z == 1) ? Ch2 : Ch3;
    } else {
        Ah += z * sA;  Bh += z * sB;
        if (NMMA == 2) Al += z * sA;
        if (EPI == 4) { Ch += z * sC;  rsum += z * M; }
        if (EPI == 5) { C  += z * sC;  rsum += z * M; }
    }

    const long long bm = (long long)blockIdx.y * 128;
    const long long bn = (long long)blockIdx.x * 128;

    const uint16_t* aSrc[2];
    aSrc[0] = Ah + bm * K;
    aSrc[1] = (NMMA == 2) ? (Al + bm * K) : aSrc[0];
    const uint16_t* bSrc = BTRANS ? (Bh + bn) : (Bh + bn * K);

    auto issue_load = [&](int it, int stg) {
        const uint32_t stage = sb + stg * STAGE_B;
        const int k0 = it * BKT;
#pragma unroll
        for (int t = 0; t < ATILES; ++t) {
            const uint16_t* src = aSrc[t] + k0;
#pragma unroll
            for (int c = 0; c < ACH / 2; ++c) {
                const int chunk = tid + c * 256;             // 0..128*ACH-1
                const int row = chunk / ACH;
                const int sub = chunk % ACH;
                cp_async16(stage + t * TILE_B + row * PITCH + sub * 16,
                           src + (long long)row * K + sub * 8);
            }
        }
        if (BTRANS) {
            // BKT rows x 256B = BKT*16 chunks
#pragma unroll
            for (int c = 0; c < BKT / 16; ++c) {
                const int chunk = tid + c * 256;
                const int row = chunk >> 4;                  // 0..BKT-1
                const int sub = chunk & 15;
                cp_async16(stage + BOFF + row * PITCH_T + sub * 16,
                           bSrc + (long long)(k0 + row) * N + sub * 8);
            }
        } else {
            const uint16_t* src = bSrc + k0;
#pragma unroll
            for (int c = 0; c < ACH / 2; ++c) {
                const int chunk = tid + c * 256;
                const int row = chunk / ACH;
                const int sub = chunk % ACH;
                cp_async16(stage + BOFF + row * PITCH + sub * 16,
                           src + (long long)row * K + sub * 8);
            }
        }
    };

    const int warpM = wid >> 2;        // 0..1  (64 rows each)
    const int warpN = wid & 3;         // 0..3  (32 cols each)
    const int aRow = warpM * 64 + (lane & 15);
    const int aOff = (lane >> 4) * 16;
    const int bRow = warpN * 32 + (lane & 7);          // non-trans
    const int bOff = ((lane >> 3) & 1) * 16;
    const int tRow = lane & 15;                        // trans
    const int tOff = warpN * 64 + (lane >> 4) * 16;

    float acc[4][4][4];
#pragma unroll
    for (int mi = 0; mi < 4; ++mi)
#pragma unroll
        for (int ni = 0; ni < 4; ++ni)
#pragma unroll
            for (int q = 0; q < 4; ++q) acc[mi][ni][q] = 0.f;

    const int niter = K / BKT;
    issue_load(0, 0); CP_COMMIT();
    issue_load(1, 1); CP_COMMIT();

    for (int it = 0; it < niter; ++it) {
        const int stg = it - (it / 3) * 3;
        CP_WAIT(1);
        __syncthreads();
        {
            const int nx = it + 2;
            if (nx < niter) issue_load(nx, nx - (nx / 3) * 3);
            CP_COMMIT();
        }

        const uint32_t stage  = sb + stg * STAGE_B;
        const uint32_t aBaseH = stage + aRow * PITCH + aOff;
        const uint32_t aBaseL = stage + TILE_B + aRow * PITCH + aOff;

#pragma unroll
        for (int ks = 0; ks < NKS; ++ks) {
            uint32_t ah[4][4], b[4][2];
#pragma unroll
            for (int mi = 0; mi < 4; ++mi)
                ldsm_x4(ah[mi], aBaseH + mi * (16 * PITCH) + ks * 32);
            if (BTRANS) {
                const uint32_t bT = stage + BOFF + (ks * 16 + tRow) * PITCH_T + tOff;
                uint32_t t4[4];
                ldsm_x4_trans(t4, bT);
                b[0][0] = t4[0]; b[0][1] = t4[1]; b[1][0] = t4[2]; b[1][1] = t4[3];
                ldsm_x4_trans(t4, bT + 32);
                b[2][0] = t4[0]; b[2][1] = t4[1]; b[3][0] = t4[2]; b[3][1] = t4[3];
            } else {
                const uint32_t bB = stage + BOFF + bRow * PITCH + bOff;
#pragma unroll
                for (int ni = 0; ni < 4; ++ni)
                    ldsm_x2(b[ni], bB + ni * (8 * PITCH) + ks * 32);
            }
#pragma unroll
            for (int mi = 0; mi < 4; ++mi)
#pragma unroll
                for (int ni = 0; ni < 4; ++ni)
                    mma_f16(acc[mi][ni], ah[mi], b[ni]);
            if (NMMA == 2) {
                uint32_t al[4][4];
#pragma unroll
                for (int mi = 0; mi < 4; ++mi)
                    ldsm_x4(al[mi], aBaseL + mi * (16 * PITCH) + ks * 32);
#pragma unroll
                for (int mi = 0; mi < 4; ++mi)
#pragma unroll
                    for (int ni = 0; ni < 4; ++ni)
                        mma_f16(acc[mi][ni], al[mi], b[ni]);
            }
        }
        __syncthreads();
    }

    // ---- epilogue ----
#pragma unroll
    for (int mi = 0; mi < 4; ++mi) {
#pragma unroll
        for (int h = 0; h < 2; ++h) {
            const long long row = bm + warpM * 64 + (lane >> 2) + mi * 16 + h * 8;
            float rs = 0.f, inv = 0.f;
            if (EPI == 5) inv = 1.f / rsum[row];
#pragma unroll
            for (int ni = 0; ni < 4; ++ni) {
                const int col = (int)bn + warpN * 32 + (lane & 3) * 2 + ni * 8;
                const float f0 = acc[mi][ni][2 * h]     * alpha;
                const float f1 = acc[mi][ni][2 * h + 1] * alpha;
                if (EPI == 2) {
                    __half2 v; v.x = __float2half_rn(f0); v.y = __float2half_rn(f1);
                    *reinterpret_cast<__half2*>(Ch + row * N + col) = v;
                } else if (EPI == 4) {
                    // f = s * log2e (folded into alpha); P = 2^f via f16x2 MUFU
                    uint32_t packed, e2;
                    asm("cvt.rn.f16x2.f32 %0, %1, %2;" : "=r"(packed) : "f"(f1), "f"(f0));
                    asm("ex2.approx.f16x2 %0, %1;" : "=r"(e2) : "r"(packed));
                    const __half2 v = *reinterpret_cast<__half2*>(&e2);
                    const float2 ff = __half22float2(v);
                    rs += ff.x + ff.y;
                    *reinterpret_cast<__half2*>(Ch + row * N + col) = v;
                } else {
                    float2 v; v.x = f0 * inv; v.y = f1 * inv;
                    *reinterpret_cast<float2*>(C + row * N + col) = v;
                }
            }
            if (EPI == 4) {
                rs += __shfl_xor_sync(0xffffffffu, rs, 1);
                rs += __shfl_xor_sync(0xffffffffu, rs, 2);
                if ((lane & 3) == 0) atomicAdd(rsum + row, rs);
            }
        }
    }
}

// ---------------------------------------------------------------------------
// fp32 -> fp16 convert (elementwise, float4 vectorized)
// ---------------------------------------------------------------------------
__global__ __launch_bounds__(256)
void cvt_f16_kernel(const float* __restrict__ in, uint16_t* __restrict__ out, int n4)
{
    const int i = blockIdx.x * blockDim.x + threadIdx.x;
    if (i >= n4) return;
    float4 v = *reinterpret_cast<const float4*>(in + 4 * (long long)i);
    __half2 h01, h23;
    h01.x = __float2half_rn(v.x); h01.y = __float2half_rn(v.y);
    h23.x = __float2half_rn(v.z); h23.y = __float2half_rn(v.w);
    *reinterpret_cast<__half2*>(out + 4 * (long long)i)     = h01;
    *reinterpret_cast<__half2*>(out + 4 * (long long)i + 2) = h23;
}

// ---------------------------------------------------------------------------
// Fused: all three W[i][o] -> W^T[o][i] fp16 transposes (z selects matrix).
// ---------------------------------------------------------------------------
__global__ __launch_bounds__(256)
void wtrans3_f16(const float* __restrict__ Wq, const float* __restrict__ Wk,
                 const float* __restrict__ Wv,
                 uint16_t* __restrict__ Tq, uint16_t* __restrict__ Tk,
                 uint16_t* __restrict__ Tv)
{
    const float* W = (blockIdx.z == 0) ? Wq : (blockIdx.z == 1) ? Wk : Wv;
    uint16_t*    T = (blockIdx.z == 0) ? Tq : (blockIdx.z == 1) ? Tk : Tv;

    __shared__ float t[32][33];
    const int bx = blockIdx.x * 32;   // o
    const int by = blockIdx.y * 32;   // i
    const int tx = threadIdx.x, ty = threadIdx.y;   // 32 x 8
#pragma unroll
    for (int r = ty; r < 32; r += 8)
        t[r][tx] = W[(by + r) * DIM + bx + tx];
    __syncthreads();
#pragma unroll
    for (int r = ty; r < 32; r += 8)
        reinterpret_cast<__half*>(T)[(bx + r) * DIM + by + tx] =
            __float2half_rn(t[tx][r]);
}

// ---------------------------------------------------------------------------
__global__ __launch_bounds__(256)
void zero_rsum(float* __restrict__ rsum)
{
    rsum[blockIdx.x * 256 + threadIdx.x] = 0.f;
}

// ---------------------------------------------------------------------------
extern "C" void kernel_launch(void* const* d_in, const int* in_sizes, int n_in,
                              void* d_out, int out_size)
{
    const float* x  = (const float*)d_in[0];
    const float* Wq = (const float*)d_in[1];
    const float* Wk = (const float*)d_in[2];
    const float* Wv = (const float*)d_in[3];
    float* out = (float*)d_out;

    uint16_t *xh, *Wqh, *Wkh, *Wvh, *Qh, *Kh, *Vh, *Ph;
    float* rsum;
    cudaGetSymbolAddress((void**)&xh, g_xh);
    cudaGetSymbolAddress((void**)&Wqh, g_Wqh);
    cudaGetSymbolAddress((void**)&Wkh, g_Wkh);
    cudaGetSymbolAddress((void**)&Wvh, g_Wvh);
    cudaGetSymbolAddress((void**)&Qh, g_Qh);
    cudaGetSymbolAddress((void**)&Kh, g_Kh);
    cudaGetSymbolAddress((void**)&Vh, g_Vh);
    cudaGetSymbolAddress((void**)&Ph, g_Ph);
    cudaGetSymbolAddress((void**)&rsum, g_RSum);

    // projections: BK=64, NT=2  -> 3 * 2 * 18432 = 110592
    constexpr int SMP = 3 * 2 * Geom<64>::TILE_B;
    // scores: BK=64, 2 tiles    -> 110592
    constexpr int SMS = 3 * 2 * Geom<64>::TILE_B;
    // PV: BK=64, A + trans B    -> 3 * (18432 + 17408) = 107520
    constexpr int SMV = 3 * (Geom<64>::TILE_B + Geom<64>::TILE_T);
    cudaFuncSetAttribute(tc_gemm<2, 1, false, true, 64>,
                         cudaFuncAttributeMaxDynamicSharedMemorySize, SMP);
    cudaFuncSetAttribute(tc_gemm<4, 1, false, false, 64>,
                         cudaFuncAttributeMaxDynamicSharedMemorySize, SMS);
    cudaFuncSetAttribute(tc_gemm<5, 1, true, false, 64>,
                         cudaFuncAttributeMaxDynamicSharedMemorySize, SMV);

    // 1. prep: convert x to fp16, transpose W to fp16, zero row sums
    cvt_f16_kernel<<<(MTOT * DIM / 4 + 255) / 256, 256>>>(x, xh, MTOT * DIM / 4);
    wtrans3_f16<<<dim3(16, 16, 3), dim3(32, 8)>>>(Wq, Wk, Wv, Wqh, Wkh, Wvh);
    zero_rsum<<<MTOT / 256, 256>>>(rsum);

    // 2. fused projections (fp16 1-MMA, BK=64): one launch, z selects Q/K/V
    dim3 gp(DIM / 128, MTOT / 128, 3);
    tc_gemm<2, 1, false, true, 64><<<gp, 256, SMP>>>(
        xh, nullptr, Wqh, Wkh, Wvh, Qh, Kh, Vh, nullptr, nullptr,
        MTOT, DIM, DIM, 0, 0, 0, 1.f);

    // 3. scores (fp16 1-MMA, BK=64) + fused 2^x exp + atomic row sums
    const float alpha_s = 0.044194173824159216f * 1.4426950408889634f;
    dim3 gs(SEQ / 128, SEQ / 128, BATCH);
    tc_gemm<4, 1, false, false, 64><<<gs, 256, SMS>>>(
        Qh, nullptr, Kh, nullptr, nullptr, Ph, nullptr, nullptr, nullptr, rsum,
        SEQ, SEQ, DIM,
        (long long)SEQ * DIM, (long long)SEQ * DIM, (long long)SEQ * SEQ, alpha_s);

    // 4. context (fp16 1-MMA, BK=64, B=V row-major via ldsm.trans)
    dim3 gv(DIM / 128, SEQ / 128, BATCH);
    tc_gemm<5, 1, true, false, 64><<<gv, 256, SMV>>>(
        Ph, nullptr, Vh, nullptr, nullptr, nullptr, nullptr, nullptr, out, rsum,
        SEQ, DIM, SEQ,
        (long long)SEQ * SEQ, (long long)SEQ * DIM, (long long)SEQ * DIM, 1.f);

    (void)in_sizes; (void)n_in; (void)out_size;
}